// round 5
// baseline (speedup 1.0000x reference)
#include <cuda_runtime.h>

#define NN 20000
#define NE 80000
#define D  128
#define ITERS 15
#define EPSLN 1e-5f
#define PA 132   // A-tile pitch: even + float4-aligned (vector k-pair loads), 4-bank row skew

// Scratch state (allocation-free rule: __device__ globals)
__device__ float g_x[NN * D];     // node features
__device__ float g_e[NE * D];     // edge features
__device__ float g_agg[NN * D];   // scatter-sum accumulator

#define SMEM_BYTES ((128 * PA + 128 * 128) * 4 + 256 * 4)

// ---------------- packed f32x2 helpers ----------------
__device__ __forceinline__ unsigned long long pack2(float lo, float hi) {
    unsigned long long r;
    asm("mov.b64 %0, {%1, %2};" : "=l"(r) : "f"(lo), "f"(hi));
    return r;
}
__device__ __forceinline__ void unpack2(unsigned long long v, float& lo, float& hi) {
    asm("mov.b64 {%0, %1}, %2;" : "=f"(lo), "=f"(hi) : "l"(v));
}
__device__ __forceinline__ void ffma2(unsigned long long& d, unsigned long long a, unsigned long long b) {
    asm("fma.rn.f32x2 %0, %1, %2, %0;" : "+l"(d) : "l"(a), "l"(b));
}

// ---------------- 128x128x128 fp32 GEMM tile (accumulate) ----------------
// 512 threads = 16(tx) x 32(ty). Micro-tile: rows r = ty + 32*i (i=0..3),
// cols c = 2*tx + 32*j (+0/+1), j=0..3. k processed in pairs (vector A loads).
__device__ __forceinline__ void gemm128(const float* __restrict__ As,
                                        const float* __restrict__ Ws,
                                        int tx, int ty,
                                        unsigned long long acc[4][4]) {
    const float* ap = As + ty * PA;
    const float* bp = Ws + 2 * tx;
#pragma unroll 4
    for (int k2 = 0; k2 < 64; ++k2) {
        float2 a2[4];
#pragma unroll
        for (int i = 0; i < 4; ++i)
            a2[i] = *reinterpret_cast<const float2*>(ap + i * 32 * PA + 2 * k2);
        unsigned long long bv0[4], bv1[4];
#pragma unroll
        for (int j = 0; j < 4; ++j) {
            bv0[j] = *reinterpret_cast<const unsigned long long*>(bp + (2 * k2) * 128 + 32 * j);
            bv1[j] = *reinterpret_cast<const unsigned long long*>(bp + (2 * k2 + 1) * 128 + 32 * j);
        }
#pragma unroll
        for (int i = 0; i < 4; ++i) {
            unsigned long long a0 = pack2(a2[i].x, a2[i].x);
            unsigned long long a1 = pack2(a2[i].y, a2[i].y);
#pragma unroll
            for (int j = 0; j < 4; ++j) {
                ffma2(acc[i][j], a0, bv0[j]);
                ffma2(acc[i][j], a1, bv1[j]);
            }
        }
    }
}

// cooperative 128x128 fp32 weight load into shared (512 threads)
__device__ __forceinline__ void load_w(const float* __restrict__ src, float* dst, int tid) {
    const float4* s4 = (const float4*)src;
    float4* d4 = (float4*)dst;
#pragma unroll
    for (int v = 0; v < 8; ++v) d4[tid + v * 512] = s4[tid + v * 512];
}

// bias + ReLU, write activation back into A-tile, reset accumulators
__device__ __forceinline__ void relu_store(unsigned long long acc[4][4],
                                           const float* __restrict__ B,
                                           float* As, int tx, int ty) {
    float b0v[4], b1v[4];
#pragma unroll
    for (int j = 0; j < 4; ++j) {
        int c = 2 * tx + 32 * j;
        b0v[j] = B[c];
        b1v[j] = B[c + 1];
    }
#pragma unroll
    for (int i = 0; i < 4; ++i) {
        int r = ty + 32 * i;
#pragma unroll
        for (int j = 0; j < 4; ++j) {
            float lo, hi;
            unpack2(acc[i][j], lo, hi);
            int c = 2 * tx + 32 * j;
            *reinterpret_cast<float2*>(As + r * PA + c) =
                make_float2(fmaxf(lo + b0v[j], 0.f), fmaxf(hi + b1v[j], 0.f));
            acc[i][j] = 0ULL;
        }
    }
}

// ---------------- fused edge MLP + LN + residual + scatter ----------------
__global__ void __launch_bounds__(512, 1)
edge_kernel(const float* __restrict__ W0, const float* __restrict__ B0,
            const float* __restrict__ W1, const float* __restrict__ B1,
            const float* __restrict__ W2, const float* __restrict__ B2,
            const float* __restrict__ G,  const float* __restrict__ Bt,
            const int* __restrict__ eidx) {
    extern __shared__ float smem[];
    float* As = smem;                    // 128 x PA
    float* Ws = smem + 128 * PA;         // 128 x 128
    int* sidx = (int*)(Ws + 128 * 128);  // src[128], dst[128]

    const int tid = threadIdx.x;
    const int tx = tid & 15, ty = tid >> 4;
    const int base = blockIdx.x * 128;
    const int lr = tid >> 2;             // 4 threads per row
    const int off = (tid & 3) * 32;

    if (tid < 128) {
        sidx[tid]       = eidx[base + tid];        // src node
        sidx[128 + tid] = eidx[NE + base + tid];   // dst node
    }
    __syncthreads();

    unsigned long long acc[4][4];
#pragma unroll
    for (int i = 0; i < 4; ++i)
#pragma unroll
        for (int j = 0; j < 4; ++j) acc[i][j] = 0ULL;

    // layer 0: e_in = [x[row], x[col], e] -> three 128x128 K-blocks
#pragma unroll 1
    for (int s = 0; s < 3; ++s) {
        const float* srcrow;
        if (s == 0)      srcrow = g_x + (size_t)sidx[lr] * D;
        else if (s == 1) srcrow = g_x + (size_t)sidx[128 + lr] * D;
        else             srcrow = g_e + (size_t)(base + lr) * D;
        float4* ad = (float4*)(As + lr * PA + off);
        const float4* sr = (const float4*)(srcrow + off);
#pragma unroll
        for (int v = 0; v < 8; ++v) ad[v] = sr[v];
        load_w(W0 + (size_t)s * 128 * 128, Ws, tid);
        __syncthreads();
        gemm128(As, Ws, tx, ty, acc);
        __syncthreads();
    }

    relu_store(acc, B0, As, tx, ty);
    load_w(W1, Ws, tid);
    __syncthreads();
    gemm128(As, Ws, tx, ty, acc);
    __syncthreads();

    relu_store(acc, B1, As, tx, ty);
    load_w(W2, Ws, tid);
    __syncthreads();
    gemm128(As, Ws, tx, ty, acc);

    // epilogue: bias, LayerNorm, residual, store, scatter-add
    float gm0[4], gm1[4], bt0[4], bt1[4], bb0[4], bb1[4];
#pragma unroll
    for (int j = 0; j < 4; ++j) {
        int c = 2 * tx + 32 * j;
        gm0[j] = G[c];  gm1[j] = G[c + 1];
        bt0[j] = Bt[c]; bt1[j] = Bt[c + 1];
        bb0[j] = B2[c]; bb1[j] = B2[c + 1];
    }
#pragma unroll
    for (int i = 0; i < 4; ++i) {
        int r = ty + 32 * i;
        int m = base + r;
        float h0[4], h1[4];
        float s1 = 0.f, s2 = 0.f;
#pragma unroll
        for (int j = 0; j < 4; ++j) {
            float lo, hi;
            unpack2(acc[i][j], lo, hi);
            lo += bb0[j]; hi += bb1[j];
            h0[j] = lo; h1[j] = hi;
            s1 += lo + hi;
            s2 += lo * lo + hi * hi;
        }
        // row-mates are the 16 lanes sharing ty (a contiguous half-warp)
#pragma unroll
        for (int o = 8; o; o >>= 1) {
            s1 += __shfl_xor_sync(0xffffffffu, s1, o);
            s2 += __shfl_xor_sync(0xffffffffu, s2, o);
        }
        float mean = s1 * (1.f / D);
        float var  = s2 * (1.f / D) - mean * mean;
        float rstd = rsqrtf(var + EPSLN);
        int dstn = sidx[128 + r];
        float* erow = g_e + (size_t)m * D;
        float* arow = g_agg + (size_t)dstn * D;
#pragma unroll
        for (int j = 0; j < 4; ++j) {
            int c = 2 * tx + 32 * j;
            float y0 = gm0[j] * (h0[j] - mean) * rstd + bt0[j] + erow[c];
            float y1 = gm1[j] * (h1[j] - mean) * rstd + bt1[j] + erow[c + 1];
            *(float2*)(erow + c) = make_float2(y0, y1);
            atomicAdd(arow + c,     y0);
            atomicAdd(arow + c + 1, y1);
        }
    }
}

// ---------------- fused node MLP + LN + residual ----------------
__global__ void __launch_bounds__(512, 1)
node_kernel(const float* __restrict__ W0, const float* __restrict__ B0,
            const float* __restrict__ W1, const float* __restrict__ B1,
            const float* __restrict__ W2, const float* __restrict__ B2,
            const float* __restrict__ G,  const float* __restrict__ Bt) {
    extern __shared__ float smem[];
    float* As = smem;
    float* Ws = smem + 128 * PA;

    const int tid = threadIdx.x;
    const int tx = tid & 15, ty = tid >> 4;
    const int base = blockIdx.x * 128;
    const int lr = tid >> 2;
    const int off = (tid & 3) * 32;

    unsigned long long acc[4][4];
#pragma unroll
    for (int i = 0; i < 4; ++i)
#pragma unroll
        for (int j = 0; j < 4; ++j) acc[i][j] = 0ULL;

    // layer 0: n_in = [x, agg]
#pragma unroll 1
    for (int s = 0; s < 2; ++s) {
        int m = base + lr;
        float4* ad = (float4*)(As + lr * PA + off);
        if (m < NN) {
            const float* srcrow = (s == 0 ? g_x : g_agg) + (size_t)m * D;
            const float4* sr = (const float4*)(srcrow + off);
#pragma unroll
            for (int v = 0; v < 8; ++v) ad[v] = sr[v];
        } else {
#pragma unroll
            for (int v = 0; v < 8; ++v) ad[v] = make_float4(0.f, 0.f, 0.f, 0.f);
        }
        load_w(W0 + (size_t)s * 128 * 128, Ws, tid);
        __syncthreads();
        gemm128(As, Ws, tx, ty, acc);
        __syncthreads();
    }

    relu_store(acc, B0, As, tx, ty);
    load_w(W1, Ws, tid);
    __syncthreads();
    gemm128(As, Ws, tx, ty, acc);
    __syncthreads();

    relu_store(acc, B1, As, tx, ty);
    load_w(W2, Ws, tid);
    __syncthreads();
    gemm128(As, Ws, tx, ty, acc);

    float gm0[4], gm1[4], bt0[4], bt1[4], bb0[4], bb1[4];
#pragma unroll
    for (int j = 0; j < 4; ++j) {
        int c = 2 * tx + 32 * j;
        gm0[j] = G[c];  gm1[j] = G[c + 1];
        bt0[j] = Bt[c]; bt1[j] = Bt[c + 1];
        bb0[j] = B2[c]; bb1[j] = B2[c + 1];
    }
#pragma unroll
    for (int i = 0; i < 4; ++i) {
        int r = ty + 32 * i;
        int m = base + r;
        float h0[4], h1[4];
        float s1 = 0.f, s2 = 0.f;
#pragma unroll
        for (int j = 0; j < 4; ++j) {
            float lo, hi;
            unpack2(acc[i][j], lo, hi);
            lo += bb0[j]; hi += bb1[j];
            h0[j] = lo; h1[j] = hi;
            s1 += lo + hi;
            s2 += lo * lo + hi * hi;
        }
#pragma unroll
        for (int o = 8; o; o >>= 1) {
            s1 += __shfl_xor_sync(0xffffffffu, s1, o);
            s2 += __shfl_xor_sync(0xffffffffu, s2, o);
        }
        float mean = s1 * (1.f / D);
        float var  = s2 * (1.f / D) - mean * mean;
        float rstd = rsqrtf(var + EPSLN);
        if (m < NN) {
            float* xrow = g_x + (size_t)m * D;
#pragma unroll
            for (int j = 0; j < 4; ++j) {
                int c = 2 * tx + 32 * j;
                float y0 = gm0[j] * (h0[j] - mean) * rstd + bt0[j] + xrow[c];
                float y1 = gm1[j] * (h1[j] - mean) * rstd + bt1[j] + xrow[c + 1];
                *(float2*)(xrow + c) = make_float2(y0, y1);
            }
        }
    }
}

// ---------------- host launch (graph-capturable) ----------------
extern "C" void kernel_launch(void* const* d_in, const int* in_sizes, int n_in,
                              void* d_out, int out_size) {
    const float* x    = (const float*)d_in[0];
    const float* ea   = (const float*)d_in[1];
    const float* eW0  = (const float*)d_in[2];
    const float* eB0  = (const float*)d_in[3];
    const float* eW1  = (const float*)d_in[4];
    const float* eB1  = (const float*)d_in[5];
    const float* eW2  = (const float*)d_in[6];
    const float* eB2  = (const float*)d_in[7];
    const float* eG   = (const float*)d_in[8];
    const float* eBt  = (const float*)d_in[9];
    const float* nW0  = (const float*)d_in[10];
    const float* nB0  = (const float*)d_in[11];
    const float* nW1  = (const float*)d_in[12];
    const float* nB1  = (const float*)d_in[13];
    const float* nW2  = (const float*)d_in[14];
    const float* nB2  = (const float*)d_in[15];
    const float* nG   = (const float*)d_in[16];
    const float* nBt  = (const float*)d_in[17];
    const int*   eidx = (const int*)d_in[18];

    float *px, *pe, *pagg;
    cudaGetSymbolAddress((void**)&px, g_x);
    cudaGetSymbolAddress((void**)&pe, g_e);
    cudaGetSymbolAddress((void**)&pagg, g_agg);

    cudaFuncSetAttribute(edge_kernel, cudaFuncAttributeMaxDynamicSharedMemorySize, SMEM_BYTES);
    cudaFuncSetAttribute(node_kernel, cudaFuncAttributeMaxDynamicSharedMemorySize, SMEM_BYTES);

    cudaMemcpyAsync(px, x,  (size_t)NN * D * sizeof(float), cudaMemcpyDeviceToDevice);
    cudaMemcpyAsync(pe, ea, (size_t)NE * D * sizeof(float), cudaMemcpyDeviceToDevice);

    for (int it = 0; it < ITERS; ++it) {
        cudaMemsetAsync(pagg, 0, (size_t)NN * D * sizeof(float));
        edge_kernel<<<NE / 128, 512, SMEM_BYTES>>>(
            eW0 + (size_t)it * 3 * D * D, eB0 + it * D,
            eW1 + (size_t)it * D * D,     eB1 + it * D,
            eW2 + (size_t)it * D * D,     eB2 + it * D,
            eG + it * D, eBt + it * D, eidx);
        node_kernel<<<(NN + 127) / 128, 512, SMEM_BYTES>>>(
            nW0 + (size_t)it * 2 * D * D, nB0 + it * D,
            nW1 + (size_t)it * D * D,     nB1 + it * D,
            nW2 + (size_t)it * D * D,     nB2 + it * D,
            nG + it * D, nBt + it * D);
    }

    cudaMemcpyAsync(d_out, px, (size_t)NN * D * sizeof(float), cudaMemcpyDeviceToDevice);
    cudaMemcpyAsync((float*)d_out + (size_t)NN * D, pe,
                    (size_t)NE * D * sizeof(float), cudaMemcpyDeviceToDevice);
}

// round 8
// speedup vs baseline: 1.7124x; 1.7124x over previous
#include <cuda_runtime.h>
#include <cuda_bf16.h>
#include <cstdint>

#define NN 20000
#define NE 80000
#define D  128
#define ITERS 15
#define EPSLN 1e-5f

#define KP  136         // bf16 pitch of A/W smem tiles (272B rows: conflict-free ldmatrix)
#define PB  272         // pitch in bytes
#define PLANE (128 * PB)   // 34816 bytes per bf16 plane

// ---------------- persistent device state ----------------
__device__ float g_x[NN * D];
__device__ float g_e[NE * D];
__device__ float g_agg[NN * D];
// 135 prepped weight tiles (eW0:45, eW1:15, eW2:15, nW0:30, nW1:15, nW2:15)
// tile = hi plane [128 n][KP bf16] + lo plane, 69632 B
#define TILE_B 69632
#define NTILES 135
__device__ __align__(16) char g_wb[(size_t)NTILES * TILE_B];

// ---------------- smem layout (bytes) ----------------
#define SM_BIAS 0        // 5*128 floats: B0,B1,B2,G,Beta
#define SM_SIDX 2560     // 256 ints
#define SM_A    3584     // Ahi plane, then Alo plane   (also fp32 staging, 128x136 floats)
#define SM_W    (SM_A + 2 * PLANE)       // 73216: Whi then Wlo
#define SMEM_TOTAL (SM_W + 2 * PLANE)    // 142848

// ---------------- helpers ----------------
__device__ __forceinline__ uint32_t smem_to_u32(const void* p) {
    uint32_t a;
    asm("{ .reg .u64 t; cvta.to.shared.u64 t, %1; cvt.u32.u64 %0, t; }" : "=r"(a) : "l"(p));
    return a;
}

__device__ __forceinline__ void ldsm4(uint32_t* r, uint32_t addr) {
    asm volatile("ldmatrix.sync.aligned.m8n8.x4.shared.b16 {%0,%1,%2,%3}, [%4];"
        : "=r"(r[0]), "=r"(r[1]), "=r"(r[2]), "=r"(r[3]) : "r"(addr));
}

__device__ __forceinline__ void mma16816(float* c, const uint32_t* a, uint32_t b0, uint32_t b1) {
    asm volatile("mma.sync.aligned.m16n8k16.row.col.f32.bf16.bf16.f32 "
        "{%0,%1,%2,%3}, {%4,%5,%6,%7}, {%8,%9}, {%0,%1,%2,%3};"
        : "+f"(c[0]), "+f"(c[1]), "+f"(c[2]), "+f"(c[3])
        : "r"(a[0]), "r"(a[1]), "r"(a[2]), "r"(a[3]), "r"(b0), "r"(b1));
}

// split 8 fp32 -> hi/lo bf16 planes (packed pairs)
__device__ __forceinline__ void cvt8(const float* v, uint4& h4, uint4& l4) {
    uint32_t h[4], l[4];
#pragma unroll
    for (int i = 0; i < 4; ++i) {
        __nv_bfloat16 a0 = __float2bfloat16(v[2 * i]);
        __nv_bfloat16 a1 = __float2bfloat16(v[2 * i + 1]);
        float r0 = v[2 * i]     - __bfloat162float(a0);
        float r1 = v[2 * i + 1] - __bfloat162float(a1);
        h[i] = (uint32_t)__bfloat16_as_ushort(a0) | ((uint32_t)__bfloat16_as_ushort(a1) << 16);
        l[i] = (uint32_t)__bfloat16_as_ushort(__float2bfloat16(r0)) |
               ((uint32_t)__bfloat16_as_ushort(__float2bfloat16(r1)) << 16);
    }
    h4 = make_uint4(h[0], h[1], h[2], h[3]);
    l4 = make_uint4(l[0], l[1], l[2], l[3]);
}
__device__ __forceinline__ void split2(float x, float y, uint32_t& h, uint32_t& l) {
    __nv_bfloat16 hx = __float2bfloat16(x), hy = __float2bfloat16(y);
    float rx = x - __bfloat162float(hx), ry = y - __bfloat162float(hy);
    h = (uint32_t)__bfloat16_as_ushort(hx) | ((uint32_t)__bfloat16_as_ushort(hy) << 16);
    l = (uint32_t)__bfloat16_as_ushort(__float2bfloat16(rx)) |
        ((uint32_t)__bfloat16_as_ushort(__float2bfloat16(ry)) << 16);
}

// gather one 64-col half-row into A hi/lo planes (row-major, pitch PB)
__device__ __forceinline__ void fill_seg(const float* srcrow, char* Ahi, int row, int cb) {
    char* Alo = Ahi + PLANE;
    if (srcrow) {
#pragma unroll
        for (int g = 0; g < 8; ++g) {
            int c0 = cb + g * 8;
            float v[8];
            *(float4*)v       = *(const float4*)(srcrow + c0);
            *(float4*)(v + 4) = *(const float4*)(srcrow + c0 + 4);
            uint4 h4, l4; cvt8(v, h4, l4);
            uint32_t o = (uint32_t)row * PB + (uint32_t)c0 * 2;
            *(uint4*)(Ahi + o) = h4; *(uint4*)(Alo + o) = l4;
        }
    } else {
        uint4 z = make_uint4(0, 0, 0, 0);
#pragma unroll
        for (int g = 0; g < 8; ++g) {
            uint32_t o = (uint32_t)row * PB + (uint32_t)(cb + g * 8) * 2;
            *(uint4*)(Ahi + o) = z; *(uint4*)(Alo + o) = z;
        }
    }
}

// copy one prepped weight tile (hi+lo) into smem
__device__ __forceinline__ void cpw(const char* src, char* dst, int tid) {
    const float4* s = (const float4*)src;
    float4* d = (float4*)dst;
#pragma unroll
    for (int i = 0; i < 17; ++i) {
        int idx = tid + i * 256;
        if (idx < TILE_B / 16) d[idx] = s[idx];
    }
}

// one k-sweep of the 128x128 tile: acc += A[plane Ab] * W[plane Wb]^T
__device__ __forceinline__ void gemm_pass(uint32_t Ab, uint32_t Wb,
                                          float (&acc)[2][8][4], int mb, int nb, int lane) {
    uint32_t arow = (uint32_t)(mb + (lane & 15));
    uint32_t aoff = (lane & 16) ? 16u : 0u;
    uint32_t brow = (uint32_t)(nb + (lane & 7) + ((lane & 16) ? 8 : 0));
    uint32_t boff = (lane & 8) ? 16u : 0u;
    uint32_t aad0 = Ab + arow * PB + aoff;
    uint32_t aad1 = aad0 + 16 * PB;
    uint32_t bad  = Wb + brow * PB + boff;
#pragma unroll
    for (int ks = 0; ks < 8; ++ks) {
        uint32_t a0[4], a1[4];
        ldsm4(a0, aad0 + 32 * ks);
        ldsm4(a1, aad1 + 32 * ks);
#pragma unroll
        for (int g = 0; g < 4; ++g) {
            uint32_t b[4];
            ldsm4(b, bad + g * 16 * PB + 32 * ks);
            mma16816(acc[0][2 * g],     a0, b[0], b[1]);
            mma16816(acc[0][2 * g + 1], a0, b[2], b[3]);
            mma16816(acc[1][2 * g],     a1, b[0], b[1]);
            mma16816(acc[1][2 * g + 1], a1, b[2], b[3]);
        }
    }
}

// 3-term bf16-split GEMM: Ahi*Whi + Ahi*Wlo + Alo*Whi
__device__ __forceinline__ void gemm3(uint32_t Au, uint32_t Wu,
                                      float (&acc)[2][8][4], int mb, int nb, int lane) {
    gemm_pass(Au,         Wu,         acc, mb, nb, lane);
    gemm_pass(Au,         Wu + PLANE, acc, mb, nb, lane);
    gemm_pass(Au + PLANE, Wu,         acc, mb, nb, lane);
}

// mid-layer: acc -> bias+relu -> bf16 split -> A planes; reset acc
__device__ __forceinline__ void epi_mid(float (&acc)[2][8][4], const float* bias,
                                        char* Ahi, int mb, int nb, int lane) {
    char* Alo = Ahi + PLANE;
    int qr = lane >> 2, qc = 2 * (lane & 3);
#pragma unroll
    for (int mt = 0; mt < 2; ++mt) {
#pragma unroll
        for (int nt = 0; nt < 8; ++nt) {
            int c = nb + 8 * nt + qc;
            float b0 = bias[c], b1 = bias[c + 1];
            int r0 = mb + 16 * mt + qr;
            float v00 = fmaxf(acc[mt][nt][0] + b0, 0.f);
            float v01 = fmaxf(acc[mt][nt][1] + b1, 0.f);
            float v10 = fmaxf(acc[mt][nt][2] + b0, 0.f);
            float v11 = fmaxf(acc[mt][nt][3] + b1, 0.f);
            uint32_t h, l;
            uint32_t o0 = (uint32_t)r0 * PB + (uint32_t)c * 2;
            split2(v00, v01, h, l);
            *(uint32_t*)(Ahi + o0) = h; *(uint32_t*)(Alo + o0) = l;
            uint32_t o1 = o0 + 8 * PB;
            split2(v10, v11, h, l);
            *(uint32_t*)(Ahi + o1) = h; *(uint32_t*)(Alo + o1) = l;
            acc[mt][nt][0] = acc[mt][nt][1] = acc[mt][nt][2] = acc[mt][nt][3] = 0.f;
        }
    }
}

// final: acc -> +bias -> fp32 staging (pitch KP floats), overlaid on A planes
__device__ __forceinline__ void epi_stage(float (&acc)[2][8][4], const float* bias,
                                          float* stage, int mb, int nb, int lane) {
    int qr = lane >> 2, qc = 2 * (lane & 3);
#pragma unroll
    for (int mt = 0; mt < 2; ++mt) {
#pragma unroll
        for (int nt = 0; nt < 8; ++nt) {
            int c = nb + 8 * nt + qc;
            float b0 = bias[c], b1 = bias[c + 1];
            int r0 = mb + 16 * mt + qr;
            *(float2*)(stage + r0 * KP + c)       = make_float2(acc[mt][nt][0] + b0, acc[mt][nt][1] + b1);
            *(float2*)(stage + (r0 + 8) * KP + c) = make_float2(acc[mt][nt][2] + b0, acc[mt][nt][3] + b1);
        }
    }
}

// ---------------- edge kernel ----------------
__global__ void __launch_bounds__(256, 1)
edge_kernel(const char* __restrict__ w0t, const char* __restrict__ w1t, const char* __restrict__ w2t,
            const float* __restrict__ B0, const float* __restrict__ B1, const float* __restrict__ B2,
            const float* __restrict__ G,  const float* __restrict__ Bt, const int* __restrict__ eidx) {
    extern __shared__ char smem[];
    float* bs = (float*)(smem + SM_BIAS);
    int* sidx = (int*)(smem + SM_SIDX);
    char* Ahi = smem + SM_A;
    char* Wsm = smem + SM_W;
    uint32_t sb = smem_to_u32(smem);
    uint32_t Au = sb + SM_A, Wu = sb + SM_W;

    const int tid = threadIdx.x, wid = tid >> 5, lane = tid & 31;
    const int base = blockIdx.x * 128;
    const int mb = (wid >> 1) * 32, nb = (wid & 1) * 64;
    const int row = tid >> 1, cb = (tid & 1) * 64;

    if (tid < 128) {
        sidx[tid]       = eidx[base + tid];
        sidx[128 + tid] = eidx[NE + base + tid];
        bs[tid]       = B0[tid];
        bs[128 + tid] = B1[tid];
        bs[256 + tid] = B2[tid];
        bs[384 + tid] = G[tid];
        bs[512 + tid] = Bt[tid];
    }
    __syncthreads();

    float acc[2][8][4];
#pragma unroll
    for (int i = 0; i < 2; ++i)
#pragma unroll
        for (int j = 0; j < 8; ++j)
#pragma unroll
            for (int q = 0; q < 4; ++q) acc[i][j][q] = 0.f;

    // layer 0: K = 384 = [x[src], x[dst], e]
#pragma unroll 1
    for (int s = 0; s < 3; ++s) {
        const float* src;
        if (s == 0)      src = g_x + (size_t)sidx[row] * D;
        else if (s == 1) src = g_x + (size_t)sidx[128 + row] * D;
        else             src = g_e + (size_t)(base + row) * D;
        fill_seg(src, Ahi, row, cb);
        cpw(w0t + (size_t)s * TILE_B, Wsm, tid);
        __syncthreads();
        gemm3(Au, Wu, acc, mb, nb, lane);
        __syncthreads();
    }

    // layer 1
    epi_mid(acc, bs, Ahi, mb, nb, lane);
    cpw(w1t, Wsm, tid);
    __syncthreads();
    gemm3(Au, Wu, acc, mb, nb, lane);
    __syncthreads();

    // layer 2
    epi_mid(acc, bs + 128, Ahi, mb, nb, lane);
    cpw(w2t, Wsm, tid);
    __syncthreads();
    gemm3(Au, Wu, acc, mb, nb, lane);
    __syncthreads();

    // final: bias into fp32 staging
    float* stage = (float*)Ahi;
    epi_stage(acc, bs + 256, stage, mb, nb, lane);
    __syncthreads();

    // LN + residual + store + scatter (coalesced; one row per warp per step)
#pragma unroll 1
    for (int r = wid; r < 128; r += 8) {
        const float* st = stage + r * KP;
        int c = lane * 4;
        float4 v = *(const float4*)(st + c);
        float s1 = v.x + v.y + v.z + v.w;
        float s2 = v.x * v.x + v.y * v.y + v.z * v.z + v.w * v.w;
#pragma unroll
        for (int o = 16; o; o >>= 1) {
            s1 += __shfl_xor_sync(0xffffffffu, s1, o);
            s2 += __shfl_xor_sync(0xffffffffu, s2, o);
        }
        float mean = s1 * (1.f / D);
        float var  = s2 * (1.f / D) - mean * mean;
        float rstd = rsqrtf(var + EPSLN);
        float4 gm = *(const float4*)(bs + 384 + c);
        float4 bt = *(const float4*)(bs + 512 + c);
        float* erow = g_e + (size_t)(base + r) * D;
        float4 res = *(const float4*)(erow + c);
        float4 y;
        y.x = gm.x * (v.x - mean) * rstd + bt.x + res.x;
        y.y = gm.y * (v.y - mean) * rstd + bt.y + res.y;
        y.z = gm.z * (v.z - mean) * rstd + bt.z + res.z;
        y.w = gm.w * (v.w - mean) * rstd + bt.w + res.w;
        *(float4*)(erow + c) = y;
        float* arow = g_agg + (size_t)sidx[128 + r] * D;
        atomicAdd(arow + c + 0, y.x);
        atomicAdd(arow + c + 1, y.y);
        atomicAdd(arow + c + 2, y.z);
        atomicAdd(arow + c + 3, y.w);
    }
}

// ---------------- node kernel ----------------
__global__ void __launch_bounds__(256, 1)
node_kernel(const char* __restrict__ w0t, const char* __restrict__ w1t, const char* __restrict__ w2t,
            const float* __restrict__ B0, const float* __restrict__ B1, const float* __restrict__ B2,
            const float* __restrict__ G,  const float* __restrict__ Bt) {
    extern __shared__ char smem[];
    float* bs = (float*)(smem + SM_BIAS);
    char* Ahi = smem + SM_A;
    char* Wsm = smem + SM_W;
    uint32_t sb = smem_to_u32(smem);
    uint32_t Au = sb + SM_A, Wu = sb + SM_W;

    const int tid = threadIdx.x, wid = tid >> 5, lane = tid & 31;
    const int base = blockIdx.x * 128;
    const int mb = (wid >> 1) * 32, nb = (wid & 1) * 64;
    const int row = tid >> 1, cb = (tid & 1) * 64;
    const int m = base + row;

    if (tid < 128) {
        bs[tid]       = B0[tid];
        bs[128 + tid] = B1[tid];
        bs[256 + tid] = B2[tid];
        bs[384 + tid] = G[tid];
        bs[512 + tid] = Bt[tid];
    }
    __syncthreads();

    float acc[2][8][4];
#pragma unroll
    for (int i = 0; i < 2; ++i)
#pragma unroll
        for (int j = 0; j < 8; ++j)
#pragma unroll
            for (int q = 0; q < 4; ++q) acc[i][j][q] = 0.f;

    // layer 0: K = 256 = [x, agg]
#pragma unroll 1
    for (int s = 0; s < 2; ++s) {
        const float* src = (m < NN) ? ((s == 0 ? g_x : g_agg) + (size_t)m * D) : (const float*)0;
        fill_seg(src, Ahi, row, cb);
        cpw(w0t + (size_t)s * TILE_B, Wsm, tid);
        __syncthreads();
        gemm3(Au, Wu, acc, mb, nb, lane);
        __syncthreads();
    }

    epi_mid(acc, bs, Ahi, mb, nb, lane);
    cpw(w1t, Wsm, tid);
    __syncthreads();
    gemm3(Au, Wu, acc, mb, nb, lane);
    __syncthreads();

    epi_mid(acc, bs + 128, Ahi, mb, nb, lane);
    cpw(w2t, Wsm, tid);
    __syncthreads();
    gemm3(Au, Wu, acc, mb, nb, lane);
    __syncthreads();

    float* stage = (float*)Ahi;
    epi_stage(acc, bs + 256, stage, mb, nb, lane);
    __syncthreads();

#pragma unroll 1
    for (int r = wid; r < 128; r += 8) {
        int mm = base + r;
        if (mm >= NN) continue;
        const float* st = stage + r * KP;
        int c = lane * 4;
        float4 v = *(const float4*)(st + c);
        float s1 = v.x + v.y + v.z + v.w;
        float s2 = v.x * v.x + v.y * v.y + v.z * v.z + v.w * v.w;
#pragma unroll
        for (int o = 16; o; o >>= 1) {
            s1 += __shfl_xor_sync(0xffffffffu, s1, o);
            s2 += __shfl_xor_sync(0xffffffffu, s2, o);
        }
        float mean = s1 * (1.f / D);
        float var  = s2 * (1.f / D) - mean * mean;
        float rstd = rsqrtf(var + EPSLN);
        float4 gm = *(const float4*)(bs + 384 + c);
        float4 bt = *(const float4*)(bs + 512 + c);
        float* xrow = g_x + (size_t)mm * D;
        float4 res = *(const float4*)(xrow + c);
        float4 y;
        y.x = gm.x * (v.x - mean) * rstd + bt.x + res.x;
        y.y = gm.y * (v.y - mean) * rstd + bt.y + res.y;
        y.z = gm.z * (v.z - mean) * rstd + bt.z + res.z;
        y.w = gm.w * (v.w - mean) * rstd + bt.w + res.w;
        *(float4*)(xrow + c) = y;
    }
}

// ---------------- weight prep: transpose + bf16 split, pitch KP ----------------
// src: consecutive [128 K][128 N] fp32 tiles; dst per tile: hi plane [n][KP] + lo plane
__global__ void __launch_bounds__(256, 1)
prep_w(const float* __restrict__ src, char* __restrict__ dst) {
    const int t = blockIdx.x, tid = threadIdx.x;
    const float* s = src + (size_t)t * 16384;
    char* hi = dst + (size_t)t * TILE_B;
    char* lo = hi + PLANE;
    const int n = tid >> 1, kb = (tid & 1) * 64;
#pragma unroll 1
    for (int g = 0; g < 8; ++g) {
        float v[8];
#pragma unroll
        for (int j = 0; j < 8; ++j) v[j] = s[(size_t)(kb + g * 8 + j) * 128 + n];
        uint4 h4, l4; cvt8(v, h4, l4);
        uint32_t o = (uint32_t)n * PB + (uint32_t)(kb + g * 8) * 2;
        *(uint4*)(hi + o) = h4; *(uint4*)(lo + o) = l4;
    }
}

// ---------------- host launch (graph-capturable) ----------------
extern "C" void kernel_launch(void* const* d_in, const int* in_sizes, int n_in,
                              void* d_out, int out_size) {
    const float* x    = (const float*)d_in[0];
    const float* ea   = (const float*)d_in[1];
    const float* eW0  = (const float*)d_in[2];
    const float* eB0  = (const float*)d_in[3];
    const float* eW1  = (const float*)d_in[4];
    const float* eB1  = (const float*)d_in[5];
    const float* eW2  = (const float*)d_in[6];
    const float* eB2  = (const float*)d_in[7];
    const float* eG   = (const float*)d_in[8];
    const float* eBt  = (const float*)d_in[9];
    const float* nW0  = (const float*)d_in[10];
    const float* nB0  = (const float*)d_in[11];
    const float* nW1  = (const float*)d_in[12];
    const float* nB1  = (const float*)d_in[13];
    const float* nW2  = (const float*)d_in[14];
    const float* nB2  = (const float*)d_in[15];
    const float* nG   = (const float*)d_in[16];
    const float* nBt  = (const float*)d_in[17];
    const int*   eidx = (const int*)d_in[18];

    float *px, *pe, *pagg;
    char* pwb;
    cudaGetSymbolAddress((void**)&px,   g_x);
    cudaGetSymbolAddress((void**)&pe,   g_e);
    cudaGetSymbolAddress((void**)&pagg, g_agg);
    cudaGetSymbolAddress((void**)&pwb,  g_wb);

    cudaFuncSetAttribute(edge_kernel, cudaFuncAttributeMaxDynamicSharedMemorySize, SMEM_TOTAL);
    cudaFuncSetAttribute(node_kernel, cudaFuncAttributeMaxDynamicSharedMemorySize, SMEM_TOTAL);

    cudaMemcpyAsync(px, x,  (size_t)NN * D * sizeof(float), cudaMemcpyDeviceToDevice);
    cudaMemcpyAsync(pe, ea, (size_t)NE * D * sizeof(float), cudaMemcpyDeviceToDevice);

    // weight prep: 135 tiles
    prep_w<<<45, 256>>>(eW0, pwb);                                // [it*3+s]
    prep_w<<<15, 256>>>(eW1, pwb + (size_t)45  * TILE_B);
    prep_w<<<15, 256>>>(eW2, pwb + (size_t)60  * TILE_B);
    prep_w<<<30, 256>>>(nW0, pwb + (size_t)75  * TILE_B);         // [it*2+s]
    prep_w<<<15, 256>>>(nW1, pwb + (size_t)105 * TILE_B);
    prep_w<<<15, 256>>>(nW2, pwb + (size_t)120 * TILE_B);

    for (int it = 0; it < ITERS; ++it) {
        cudaMemsetAsync(pagg, 0, (size_t)NN * D * sizeof(float));
        edge_kernel<<<NE / 128, 256, SMEM_TOTAL>>>(
            pwb + (size_t)(it * 3)      * TILE_B,
            pwb + (size_t)(45 + it)     * TILE_B,
            pwb + (size_t)(60 + it)     * TILE_B,
            eB0 + it * D, eB1 + it * D, eB2 + it * D,
            eG + it * D, eBt + it * D, eidx);
        node_kernel<<<(NN + 127) / 128, 256, SMEM_TOTAL>>>(
            pwb + (size_t)(75 + it * 2) * TILE_B,
            pwb + (size_t)(105 + it)    * TILE_B,
            pwb + (size_t)(120 + it)    * TILE_B,
            nB0 + it * D, nB1 + it * D, nB2 + it * D,
            nG + it * D, nBt + it * D);
    }

    cudaMemcpyAsync(d_out, px, (size_t)NN * D * sizeof(float), cudaMemcpyDeviceToDevice);
    cudaMemcpyAsync((float*)d_out + (size_t)NN * D, pe,
                    (size_t)NE * D * sizeof(float), cudaMemcpyDeviceToDevice);
}

// round 9
// speedup vs baseline: 2.0711x; 1.2095x over previous
#include <cuda_runtime.h>
#include <cuda_bf16.h>
#include <cstdint>

#define NN 20000
#define NE 80000
#define D  128
#define ITERS 15
#define EPSLN 1e-5f

#define KP  136          // bf16 pitch (272B rows: conflict-free ldmatrix, 16B aligned)
#define PB  272
#define PLANE_A (64 * PB)    // 17408 B per A bf16 plane (64-row tile)
#define PLANE_W (128 * PB)   // 34816 B per W bf16 plane

// ---------------- persistent device state ----------------
__device__ float g_x[NN * D];
__device__ float g_e[NE * D];
__device__ float g_agg[NN * D];
// 135 prepped weight tiles: hi plane [128 n][KP bf16] + lo plane
#define TILE_B 69632
#define NTILES 135
__device__ __align__(16) char g_wb[(size_t)NTILES * TILE_B];

// ---------------- smem layout (bytes) ----------------
#define SM_BIAS 0        // 5*128 floats: B0,B1,B2,G,Beta
#define SM_SIDX 2560     // 128 ints (edge: src[64], dst[64])
#define SM_A    3584     // Ahi, Alo (2*17408) ; doubles as fp32 staging 64x136
#define SM_W    (SM_A + 2 * PLANE_A)      // 38400: Whi, Wlo
#define SMEM_TOTAL (SM_W + 2 * PLANE_W)   // 108032  (x2 CTAs = 216KB < 227KB)

// ---------------- helpers ----------------
__device__ __forceinline__ uint32_t smem_to_u32(const void* p) {
    uint32_t a;
    asm("{ .reg .u64 t; cvta.to.shared.u64 t, %1; cvt.u32.u64 %0, t; }" : "=r"(a) : "l"(p));
    return a;
}
__device__ __forceinline__ void ldsm4(uint32_t* r, uint32_t addr) {
    asm volatile("ldmatrix.sync.aligned.m8n8.x4.shared.b16 {%0,%1,%2,%3}, [%4];"
        : "=r"(r[0]), "=r"(r[1]), "=r"(r[2]), "=r"(r[3]) : "r"(addr));
}
__device__ __forceinline__ void mma16816(float* c, const uint32_t* a, uint32_t b0, uint32_t b1) {
    asm volatile("mma.sync.aligned.m16n8k16.row.col.f32.bf16.bf16.f32 "
        "{%0,%1,%2,%3}, {%4,%5,%6,%7}, {%8,%9}, {%0,%1,%2,%3};"
        : "+f"(c[0]), "+f"(c[1]), "+f"(c[2]), "+f"(c[3])
        : "r"(a[0]), "r"(a[1]), "r"(a[2]), "r"(a[3]), "r"(b0), "r"(b1));
}

__device__ __forceinline__ void cvt8(const float* v, uint4& h4, uint4& l4) {
    uint32_t h[4], l[4];
#pragma unroll
    for (int i = 0; i < 4; ++i) {
        __nv_bfloat16 a0 = __float2bfloat16(v[2 * i]);
        __nv_bfloat16 a1 = __float2bfloat16(v[2 * i + 1]);
        float r0 = v[2 * i]     - __bfloat162float(a0);
        float r1 = v[2 * i + 1] - __bfloat162float(a1);
        h[i] = (uint32_t)__bfloat16_as_ushort(a0) | ((uint32_t)__bfloat16_as_ushort(a1) << 16);
        l[i] = (uint32_t)__bfloat16_as_ushort(__float2bfloat16(r0)) |
               ((uint32_t)__bfloat16_as_ushort(__float2bfloat16(r1)) << 16);
    }
    h4 = make_uint4(h[0], h[1], h[2], h[3]);
    l4 = make_uint4(l[0], l[1], l[2], l[3]);
}
__device__ __forceinline__ void split2(float x, float y, uint32_t& h, uint32_t& l) {
    __nv_bfloat16 hx = __float2bfloat16(x), hy = __float2bfloat16(y);
    float rx = x - __bfloat162float(hx), ry = y - __bfloat162float(hy);
    h = (uint32_t)__bfloat16_as_ushort(hx) | ((uint32_t)__bfloat16_as_ushort(hy) << 16);
    l = (uint32_t)__bfloat16_as_ushort(__float2bfloat16(rx)) |
        ((uint32_t)__bfloat16_as_ushort(__float2bfloat16(ry)) << 16);
}

// gather one 32-col quarter-row into A hi/lo planes (64-row tile, 4 thr/row)
__device__ __forceinline__ void fill_seg(const float* srcrow, char* Ahi, int row, int cb) {
    char* Alo = Ahi + PLANE_A;
    if (srcrow) {
#pragma unroll
        for (int g = 0; g < 4; ++g) {
            int c0 = cb + g * 8;
            float v[8];
            *(float4*)v       = *(const float4*)(srcrow + c0);
            *(float4*)(v + 4) = *(const float4*)(srcrow + c0 + 4);
            uint4 h4, l4; cvt8(v, h4, l4);
            uint32_t o = (uint32_t)row * PB + (uint32_t)c0 * 2;
            *(uint4*)(Ahi + o) = h4; *(uint4*)(Alo + o) = l4;
        }
    } else {
        uint4 z = make_uint4(0, 0, 0, 0);
#pragma unroll
        for (int g = 0; g < 4; ++g) {
            uint32_t o = (uint32_t)row * PB + (uint32_t)(cb + g * 8) * 2;
            *(uint4*)(Ahi + o) = z; *(uint4*)(Alo + o) = z;
        }
    }
}

// copy one prepped weight tile (hi+lo, 68KB) into smem
__device__ __forceinline__ void cpw(const char* src, char* dst, int tid) {
    const float4* s = (const float4*)src;
    float4* d = (float4*)dst;
#pragma unroll
    for (int i = 0; i < 17; ++i) {
        int idx = tid + i * 256;
        if (idx < TILE_B / 16) d[idx] = s[idx];
    }
}

// merged 3-term bf16-split GEMM: acc += Ahi*Whi + Ahi*Wlo + Alo*Whi
// warp tile m32 x n32 ; warp grid 2(m) x 4(n)
__device__ __forceinline__ void gemm3(uint32_t Au, uint32_t Wu,
                                      float (&acc)[2][4][4], int mb, int nb, int lane) {
    uint32_t arow = (uint32_t)(mb + (lane & 15));
    uint32_t aoff = (lane & 16) ? 16u : 0u;
    uint32_t ah = Au + arow * PB + aoff;
    uint32_t al = ah + PLANE_A;
    uint32_t brow = (uint32_t)(nb + (lane & 7) + ((lane & 16) ? 8 : 0));
    uint32_t boff = (lane & 8) ? 16u : 0u;
    uint32_t bh = Wu + brow * PB + boff;
    uint32_t bl = bh + PLANE_W;
#pragma unroll
    for (int ks = 0; ks < 8; ++ks) {
        uint32_t kadd = 32u * ks;
        uint32_t a0h[4], a1h[4], a0l[4], a1l[4];
        ldsm4(a0h, ah + kadd);
        ldsm4(a1h, ah + 16 * PB + kadd);
        ldsm4(a0l, al + kadd);
        ldsm4(a1l, al + 16 * PB + kadd);
        uint32_t b0h[4], b1h[4], b0l[4], b1l[4];
        ldsm4(b0h, bh + kadd);
        ldsm4(b1h, bh + 16 * PB + kadd);
        ldsm4(b0l, bl + kadd);
        ldsm4(b1l, bl + 16 * PB + kadd);
        // hi * hi
        mma16816(acc[0][0], a0h, b0h[0], b0h[1]);
        mma16816(acc[0][1], a0h, b0h[2], b0h[3]);
        mma16816(acc[0][2], a0h, b1h[0], b1h[1]);
        mma16816(acc[0][3], a0h, b1h[2], b1h[3]);
        mma16816(acc[1][0], a1h, b0h[0], b0h[1]);
        mma16816(acc[1][1], a1h, b0h[2], b0h[3]);
        mma16816(acc[1][2], a1h, b1h[0], b1h[1]);
        mma16816(acc[1][3], a1h, b1h[2], b1h[3]);
        // hi * lo
        mma16816(acc[0][0], a0h, b0l[0], b0l[1]);
        mma16816(acc[0][1], a0h, b0l[2], b0l[3]);
        mma16816(acc[0][2], a0h, b1l[0], b1l[1]);
        mma16816(acc[0][3], a0h, b1l[2], b1l[3]);
        mma16816(acc[1][0], a1h, b0l[0], b0l[1]);
        mma16816(acc[1][1], a1h, b0l[2], b0l[3]);
        mma16816(acc[1][2], a1h, b1l[0], b1l[1]);
        mma16816(acc[1][3], a1h, b1l[2], b1l[3]);
        // lo * hi
        mma16816(acc[0][0], a0l, b0h[0], b0h[1]);
        mma16816(acc[0][1], a0l, b0h[2], b0h[3]);
        mma16816(acc[0][2], a0l, b1h[0], b1h[1]);
        mma16816(acc[0][3], a0l, b1h[2], b1h[3]);
        mma16816(acc[1][0], a1l, b0h[0], b0h[1]);
        mma16816(acc[1][1], a1l, b0h[2], b0h[3]);
        mma16816(acc[1][2], a1l, b1h[0], b1h[1]);
        mma16816(acc[1][3], a1l, b1h[2], b1h[3]);
    }
}

// mid-layer: acc -> bias+relu -> bf16 split -> A planes; reset acc
__device__ __forceinline__ void epi_mid(float (&acc)[2][4][4], const float* bias,
                                        char* Ahi, int mb, int nb, int lane) {
    char* Alo = Ahi + PLANE_A;
    int qr = lane >> 2, qc = 2 * (lane & 3);
#pragma unroll
    for (int mt = 0; mt < 2; ++mt) {
#pragma unroll
        for (int nt = 0; nt < 4; ++nt) {
            int c = nb + 8 * nt + qc;
            float b0 = bias[c], b1 = bias[c + 1];
            int r0 = mb + 16 * mt + qr;
            float v00 = fmaxf(acc[mt][nt][0] + b0, 0.f);
            float v01 = fmaxf(acc[mt][nt][1] + b1, 0.f);
            float v10 = fmaxf(acc[mt][nt][2] + b0, 0.f);
            float v11 = fmaxf(acc[mt][nt][3] + b1, 0.f);
            uint32_t h, l;
            uint32_t o0 = (uint32_t)r0 * PB + (uint32_t)c * 2;
            split2(v00, v01, h, l);
            *(uint32_t*)(Ahi + o0) = h; *(uint32_t*)(Alo + o0) = l;
            uint32_t o1 = o0 + 8 * PB;
            split2(v10, v11, h, l);
            *(uint32_t*)(Ahi + o1) = h; *(uint32_t*)(Alo + o1) = l;
            acc[mt][nt][0] = acc[mt][nt][1] = acc[mt][nt][2] = acc[mt][nt][3] = 0.f;
        }
    }
}

// final: acc -> +bias -> fp32 staging (pitch KP floats, overlaid on A planes)
__device__ __forceinline__ void epi_stage(float (&acc)[2][4][4], const float* bias,
                                          float* stage, int mb, int nb, int lane) {
    int qr = lane >> 2, qc = 2 * (lane & 3);
#pragma unroll
    for (int mt = 0; mt < 2; ++mt) {
#pragma unroll
        for (int nt = 0; nt < 4; ++nt) {
            int c = nb + 8 * nt + qc;
            float b0 = bias[c], b1 = bias[c + 1];
            int r0 = mb + 16 * mt + qr;
            *(float2*)(stage + r0 * KP + c)       = make_float2(acc[mt][nt][0] + b0, acc[mt][nt][1] + b1);
            *(float2*)(stage + (r0 + 8) * KP + c) = make_float2(acc[mt][nt][2] + b0, acc[mt][nt][3] + b1);
        }
    }
}

// ---------------- edge kernel (64-edge tile) ----------------
__global__ void __launch_bounds__(256, 2)
edge_kernel(const char* __restrict__ w0t, const char* __restrict__ w1t, const char* __restrict__ w2t,
            const float* __restrict__ B0, const float* __restrict__ B1, const float* __restrict__ B2,
            const float* __restrict__ G,  const float* __restrict__ Bt, const int* __restrict__ eidx) {
    extern __shared__ char smem[];
    float* bs = (float*)(smem + SM_BIAS);
    int* sidx = (int*)(smem + SM_SIDX);
    char* Ahi = smem + SM_A;
    char* Wsm = smem + SM_W;
    uint32_t sb = smem_to_u32(smem);
    uint32_t Au = sb + SM_A, Wu = sb + SM_W;

    const int tid = threadIdx.x, wid = tid >> 5, lane = tid & 31;
    const int base = blockIdx.x * 64;
    const int mb = (wid >> 2) * 32, nb = (wid & 3) * 32;
    const int row = tid >> 2, cb = (tid & 3) * 32;

    if (tid < 64) {
        sidx[tid]      = eidx[base + tid];
        sidx[64 + tid] = eidx[NE + base + tid];
    }
    if (tid < 128) {
        bs[tid]       = B0[tid];
        bs[128 + tid] = B1[tid];
        bs[256 + tid] = B2[tid];
        bs[384 + tid] = G[tid];
        bs[512 + tid] = Bt[tid];
    }
    __syncthreads();

    float acc[2][4][4];
#pragma unroll
    for (int i = 0; i < 2; ++i)
#pragma unroll
        for (int j = 0; j < 4; ++j)
#pragma unroll
            for (int q = 0; q < 4; ++q) acc[i][j][q] = 0.f;

    // layer 0: K = 384 = [x[src], x[dst], e]
#pragma unroll 1
    for (int s = 0; s < 3; ++s) {
        const float* src;
        if (s == 0)      src = g_x + (size_t)sidx[row] * D;
        else if (s == 1) src = g_x + (size_t)sidx[64 + row] * D;
        else             src = g_e + (size_t)(base + row) * D;
        fill_seg(src, Ahi, row, cb);
        cpw(w0t + (size_t)s * TILE_B, Wsm, tid);
        __syncthreads();
        gemm3(Au, Wu, acc, mb, nb, lane);
        __syncthreads();
    }

    epi_mid(acc, bs, Ahi, mb, nb, lane);
    cpw(w1t, Wsm, tid);
    __syncthreads();
    gemm3(Au, Wu, acc, mb, nb, lane);
    __syncthreads();

    epi_mid(acc, bs + 128, Ahi, mb, nb, lane);
    cpw(w2t, Wsm, tid);
    __syncthreads();
    gemm3(Au, Wu, acc, mb, nb, lane);
    __syncthreads();

    float* stage = (float*)Ahi;
    epi_stage(acc, bs + 256, stage, mb, nb, lane);
    __syncthreads();

    // LN + residual + store + scatter (one row per warp per step)
#pragma unroll 1
    for (int r = wid; r < 64; r += 8) {
        const float* st = stage + r * KP;
        int c = lane * 4;
        float4 v = *(const float4*)(st + c);
        float s1 = v.x + v.y + v.z + v.w;
        float s2 = v.x * v.x + v.y * v.y + v.z * v.z + v.w * v.w;
#pragma unroll
        for (int o = 16; o; o >>= 1) {
            s1 += __shfl_xor_sync(0xffffffffu, s1, o);
            s2 += __shfl_xor_sync(0xffffffffu, s2, o);
        }
        float mean = s1 * (1.f / D);
        float var  = s2 * (1.f / D) - mean * mean;
        float rstd = rsqrtf(var + EPSLN);
        float4 gm = *(const float4*)(bs + 384 + c);
        float4 bt = *(const float4*)(bs + 512 + c);
        float* erow = g_e + (size_t)(base + r) * D;
        float4 res = *(const float4*)(erow + c);
        float4 y;
        y.x = gm.x * (v.x - mean) * rstd + bt.x + res.x;
        y.y = gm.y * (v.y - mean) * rstd + bt.y + res.y;
        y.z = gm.z * (v.z - mean) * rstd + bt.z + res.z;
        y.w = gm.w * (v.w - mean) * rstd + bt.w + res.w;
        *(float4*)(erow + c) = y;
        float* arow = g_agg + (size_t)sidx[64 + r] * D;
        atomicAdd(arow + c + 0, y.x);
        atomicAdd(arow + c + 1, y.y);
        atomicAdd(arow + c + 2, y.z);
        atomicAdd(arow + c + 3, y.w);
    }
}

// ---------------- node kernel (64-node tile) ----------------
__global__ void __launch_bounds__(256, 2)
node_kernel(const char* __restrict__ w0t, const char* __restrict__ w1t, const char* __restrict__ w2t,
            const float* __restrict__ B0, const float* __restrict__ B1, const float* __restrict__ B2,
            const float* __restrict__ G,  const float* __restrict__ Bt) {
    extern __shared__ char smem[];
    float* bs = (float*)(smem + SM_BIAS);
    char* Ahi = smem + SM_A;
    char* Wsm = smem + SM_W;
    uint32_t sb = smem_to_u32(smem);
    uint32_t Au = sb + SM_A, Wu = sb + SM_W;

    const int tid = threadIdx.x, wid = tid >> 5, lane = tid & 31;
    const int base = blockIdx.x * 64;
    const int mb = (wid >> 2) * 32, nb = (wid & 3) * 32;
    const int row = tid >> 2, cb = (tid & 3) * 32;
    const int m = base + row;

    if (tid < 128) {
        bs[tid]       = B0[tid];
        bs[128 + tid] = B1[tid];
        bs[256 + tid] = B2[tid];
        bs[384 + tid] = G[tid];
        bs[512 + tid] = Bt[tid];
    }
    __syncthreads();

    float acc[2][4][4];
#pragma unroll
    for (int i = 0; i < 2; ++i)
#pragma unroll
        for (int j = 0; j < 4; ++j)
#pragma unroll
            for (int q = 0; q < 4; ++q) acc[i][j][q] = 0.f;

    // layer 0: K = 256 = [x, agg]
#pragma unroll 1
    for (int s = 0; s < 2; ++s) {
        const float* src = (m < NN) ? ((s == 0 ? g_x : g_agg) + (size_t)m * D) : (const float*)0;
        fill_seg(src, Ahi, row, cb);
        cpw(w0t + (size_t)s * TILE_B, Wsm, tid);
        __syncthreads();
        gemm3(Au, Wu, acc, mb, nb, lane);
        __syncthreads();
    }

    epi_mid(acc, bs, Ahi, mb, nb, lane);
    cpw(w1t, Wsm, tid);
    __syncthreads();
    gemm3(Au, Wu, acc, mb, nb, lane);
    __syncthreads();

    epi_mid(acc, bs + 128, Ahi, mb, nb, lane);
    cpw(w2t, Wsm, tid);
    __syncthreads();
    gemm3(Au, Wu, acc, mb, nb, lane);
    __syncthreads();

    float* stage = (float*)Ahi;
    epi_stage(acc, bs + 256, stage, mb, nb, lane);
    __syncthreads();

#pragma unroll 1
    for (int r = wid; r < 64; r += 8) {
        int mm = base + r;
        if (mm >= NN) continue;
        const float* st = stage + r * KP;
        int c = lane * 4;
        float4 v = *(const float4*)(st + c);
        float s1 = v.x + v.y + v.z + v.w;
        float s2 = v.x * v.x + v.y * v.y + v.z * v.z + v.w * v.w;
#pragma unroll
        for (int o = 16; o; o >>= 1) {
            s1 += __shfl_xor_sync(0xffffffffu, s1, o);
            s2 += __shfl_xor_sync(0xffffffffu, s2, o);
        }
        float mean = s1 * (1.f / D);
        float var  = s2 * (1.f / D) - mean * mean;
        float rstd = rsqrtf(var + EPSLN);
        float4 gm = *(const float4*)(bs + 384 + c);
        float4 bt = *(const float4*)(bs + 512 + c);
        float* xrow = g_x + (size_t)mm * D;
        float4 res = *(const float4*)(xrow + c);
        float4 y;
        y.x = gm.x * (v.x - mean) * rstd + bt.x + res.x;
        y.y = gm.y * (v.y - mean) * rstd + bt.y + res.y;
        y.z = gm.z * (v.z - mean) * rstd + bt.z + res.z;
        y.w = gm.w * (v.w - mean) * rstd + bt.w + res.w;
        *(float4*)(xrow + c) = y;
    }
}

// ---------------- weight prep: transpose + bf16 split, pitch KP ----------------
__global__ void __launch_bounds__(256, 1)
prep_w(const float* __restrict__ src, char* __restrict__ dst) {
    const int t = blockIdx.x, tid = threadIdx.x;
    const float* s = src + (size_t)t * 16384;
    char* hi = dst + (size_t)t * TILE_B;
    char* lo = hi + PLANE_W;
    const int n = tid >> 1, kb = (tid & 1) * 64;
#pragma unroll 1
    for (int g = 0; g < 8; ++g) {
        float v[8];
#pragma unroll
        for (int j = 0; j < 8; ++j) v[j] = s[(size_t)(kb + g * 8 + j) * 128 + n];
        uint4 h4, l4; cvt8(v, h4, l4);
        uint32_t o = (uint32_t)n * PB + (uint32_t)(kb + g * 8) * 2;
        *(uint4*)(hi + o) = h4; *(uint4*)(lo + o) = l4;
    }
}

// ---------------- host launch (graph-capturable) ----------------
extern "C" void kernel_launch(void* const* d_in, const int* in_sizes, int n_in,
                              void* d_out, int out_size) {
    const float* x    = (const float*)d_in[0];
    const float* ea   = (const float*)d_in[1];
    const float* eW0  = (const float*)d_in[2];
    const float* eB0  = (const float*)d_in[3];
    const float* eW1  = (const float*)d_in[4];
    const float* eB1  = (const float*)d_in[5];
    const float* eW2  = (const float*)d_in[6];
    const float* eB2  = (const float*)d_in[7];
    const float* eG   = (const float*)d_in[8];
    const float* eBt  = (const float*)d_in[9];
    const float* nW0  = (const float*)d_in[10];
    const float* nB0  = (const float*)d_in[11];
    const float* nW1  = (const float*)d_in[12];
    const float* nB1  = (const float*)d_in[13];
    const float* nW2  = (const float*)d_in[14];
    const float* nB2  = (const float*)d_in[15];
    const float* nG   = (const float*)d_in[16];
    const float* nBt  = (const float*)d_in[17];
    const int*   eidx = (const int*)d_in[18];

    float *px, *pe, *pagg;
    char* pwb;
    cudaGetSymbolAddress((void**)&px,   g_x);
    cudaGetSymbolAddress((void**)&pe,   g_e);
    cudaGetSymbolAddress((void**)&pagg, g_agg);
    cudaGetSymbolAddress((void**)&pwb,  g_wb);

    cudaFuncSetAttribute(edge_kernel, cudaFuncAttributeMaxDynamicSharedMemorySize, SMEM_TOTAL);
    cudaFuncSetAttribute(node_kernel, cudaFuncAttributeMaxDynamicSharedMemorySize, SMEM_TOTAL);

    cudaMemcpyAsync(px, x,  (size_t)NN * D * sizeof(float), cudaMemcpyDeviceToDevice);
    cudaMemcpyAsync(pe, ea, (size_t)NE * D * sizeof(float), cudaMemcpyDeviceToDevice);

    // weight prep: 135 tiles
    prep_w<<<45, 256>>>(eW0, pwb);                                // [it*3+s]
    prep_w<<<15, 256>>>(eW1, pwb + (size_t)45  * TILE_B);
    prep_w<<<15, 256>>>(eW2, pwb + (size_t)60  * TILE_B);
    prep_w<<<30, 256>>>(nW0, pwb + (size_t)75  * TILE_B);         // [it*2+s]
    prep_w<<<15, 256>>>(nW1, pwb + (size_t)105 * TILE_B);
    prep_w<<<15, 256>>>(nW2, pwb + (size_t)120 * TILE_B);

    for (int it = 0; it < ITERS; ++it) {
        cudaMemsetAsync(pagg, 0, (size_t)NN * D * sizeof(float));
        edge_kernel<<<NE / 64, 256, SMEM_TOTAL>>>(
            pwb + (size_t)(it * 3)      * TILE_B,
            pwb + (size_t)(45 + it)     * TILE_B,
            pwb + (size_t)(60 + it)     * TILE_B,
            eB0 + it * D, eB1 + it * D, eB2 + it * D,
            eG + it * D, eBt + it * D, eidx);
        node_kernel<<<(NN + 63) / 64, 256, SMEM_TOTAL>>>(
            pwb + (size_t)(75 + it * 2) * TILE_B,
            pwb + (size_t)(105 + it)    * TILE_B,
            pwb + (size_t)(120 + it)    * TILE_B,
            nB0 + it * D, nB1 + it * D, nB2 + it * D,
            nG + it * D, nBt + it * D);
    }

    cudaMemcpyAsync(d_out, px, (size_t)NN * D * sizeof(float), cudaMemcpyDeviceToDevice);
    cudaMemcpyAsync((float*)d_out + (size_t)NN * D, pe,
                    (size_t)NE * D * sizeof(float), cudaMemcpyDeviceToDevice);
}

// round 14
// speedup vs baseline: 2.0784x; 1.0035x over previous
#include <cuda_runtime.h>
#include <cuda_bf16.h>
#include <cstdint>

#define NN 20000
#define NE 80000
#define D  128
#define ITERS 15
#define EPSLN 1e-5f

#define KP  136          // bf16 pitch (272B rows: conflict-free ldmatrix, 16B aligned)
#define PB  272
#define PLANE_A (64 * PB)    // 17408 B per A bf16 plane (64-row tile)
#define PLANE_W (128 * PB)   // 34816 B per W bf16 plane

// ---------------- persistent device state ----------------
__device__ float g_x[NN * D];
__device__ float g_e[NE * D];
// CSR of edges grouped by destination node (built once per launch)
__device__ int g_off[NN + 1];
__device__ int g_cur[NN];
__device__ int g_csr[NE];
// 135 prepped weight tiles: hi plane [128 n][KP bf16] + lo plane
#define TILE_B 69632
#define NTILES 135
__device__ __align__(16) char g_wb[(size_t)NTILES * TILE_B];

// ---------------- smem layout (bytes) ----------------
#define SM_BIAS 0        // 5*128 floats: B0,B1,B2,G,Beta
#define SM_SIDX 2560     // 128 ints (edge: src[64], dst[64])
#define SM_A    3584     // Ahi, Alo (2*17408) ; doubles as fp32 staging 64x136
#define SM_W    (SM_A + 2 * PLANE_A)      // 38400: Whi, Wlo
#define SMEM_TOTAL (SM_W + 2 * PLANE_W)   // 108032  (x2 CTAs = 216KB < 227KB)

// ---------------- helpers ----------------
__device__ __forceinline__ uint32_t smem_to_u32(const void* p) {
    uint32_t a;
    asm("{ .reg .u64 t; cvta.to.shared.u64 t, %1; cvt.u32.u64 %0, t; }" : "=r"(a) : "l"(p));
    return a;
}
__device__ __forceinline__ void ldsm4(uint32_t* r, uint32_t addr) {
    asm volatile("ldmatrix.sync.aligned.m8n8.x4.shared.b16 {%0,%1,%2,%3}, [%4];"
        : "=r"(r[0]), "=r"(r[1]), "=r"(r[2]), "=r"(r[3]) : "r"(addr));
}
__device__ __forceinline__ void mma16816(float* c, const uint32_t* a, uint32_t b0, uint32_t b1) {
    asm volatile("mma.sync.aligned.m16n8k16.row.col.f32.bf16.bf16.f32 "
        "{%0,%1,%2,%3}, {%4,%5,%6,%7}, {%8,%9}, {%0,%1,%2,%3};"
        : "+f"(c[0]), "+f"(c[1]), "+f"(c[2]), "+f"(c[3])
        : "r"(a[0]), "r"(a[1]), "r"(a[2]), "r"(a[3]), "r"(b0), "r"(b1));
}

__device__ __forceinline__ void cvt8(const float* v, uint4& h4, uint4& l4) {
    uint32_t h[4], l[4];
#pragma unroll
    for (int i = 0; i < 4; ++i) {
        __nv_bfloat16 a0 = __float2bfloat16(v[2 * i]);
        __nv_bfloat16 a1 = __float2bfloat16(v[2 * i + 1]);
        float r0 = v[2 * i]     - __bfloat162float(a0);
        float r1 = v[2 * i + 1] - __bfloat162float(a1);
        h[i] = (uint32_t)__bfloat16_as_ushort(a0) | ((uint32_t)__bfloat16_as_ushort(a1) << 16);
        l[i] = (uint32_t)__bfloat16_as_ushort(__float2bfloat16(r0)) |
               ((uint32_t)__bfloat16_as_ushort(__float2bfloat16(r1)) << 16);
    }
    h4 = make_uint4(h[0], h[1], h[2], h[3]);
    l4 = make_uint4(l[0], l[1], l[2], l[3]);
}
__device__ __forceinline__ void split2(float x, float y, uint32_t& h, uint32_t& l) {
    __nv_bfloat16 hx = __float2bfloat16(x), hy = __float2bfloat16(y);
    float rx = x - __bfloat162float(hx), ry = y - __bfloat162float(hy);
    h = (uint32_t)__bfloat16_as_ushort(hx) | ((uint32_t)__bfloat16_as_ushort(hy) << 16);
    l = (uint32_t)__bfloat16_as_ushort(__float2bfloat16(rx)) |
        ((uint32_t)__bfloat16_as_ushort(__float2bfloat16(ry)) << 16);
}

// write 32 fp32 values into the A hi/lo planes at (row, cb)
__device__ __forceinline__ void store_seg(const float* v, char* Ahi, int row, int cb) {
    char* Alo = Ahi + PLANE_A;
#pragma unroll
    for (int g = 0; g < 4; ++g) {
        uint4 h4, l4; cvt8(v + g * 8, h4, l4);
        uint32_t o = (uint32_t)row * PB + (uint32_t)(cb + g * 8) * 2;
        *(uint4*)(Ahi + o) = h4; *(uint4*)(Alo + o) = l4;
    }
}

// gather one 32-col quarter-row into A hi/lo planes (64-row tile, 4 thr/row)
__device__ __forceinline__ void fill_seg(const float* srcrow, char* Ahi, int row, int cb) {
    if (srcrow) {
        float v[32];
#pragma unroll
        for (int g = 0; g < 8; ++g) *(float4*)(v + g * 4) = *(const float4*)(srcrow + cb + g * 4);
        store_seg(v, Ahi, row, cb);
    } else {
        char* Alo = Ahi + PLANE_A;
        uint4 z = make_uint4(0, 0, 0, 0);
#pragma unroll
        for (int g = 0; g < 4; ++g) {
            uint32_t o = (uint32_t)row * PB + (uint32_t)(cb + g * 8) * 2;
            *(uint4*)(Ahi + o) = z; *(uint4*)(Alo + o) = z;
        }
    }
}

// copy one prepped weight tile (hi+lo, 68KB) into smem
__device__ __forceinline__ void cpw(const char* src, char* dst, int tid) {
    const float4* s = (const float4*)src;
    float4* d = (float4*)dst;
#pragma unroll
    for (int i = 0; i < 17; ++i) {
        int idx = tid + i * 256;
        if (idx < TILE_B / 16) d[idx] = s[idx];
    }
}

// merged 3-term bf16-split GEMM: acc += Ahi*Whi + Ahi*Wlo + Alo*Whi
// warp tile m32 x n32 ; warp grid 2(m) x 4(n)
__device__ __forceinline__ void gemm3(uint32_t Au, uint32_t Wu,
                                      float (&acc)[2][4][4], int mb, int nb, int lane) {
    uint32_t arow = (uint32_t)(mb + (lane & 15));
    uint32_t aoff = (lane & 16) ? 16u : 0u;
    uint32_t ah = Au + arow * PB + aoff;
    uint32_t al = ah + PLANE_A;
    uint32_t brow = (uint32_t)(nb + (lane & 7) + ((lane & 16) ? 8 : 0));
    uint32_t boff = (lane & 8) ? 16u : 0u;
    uint32_t bh = Wu + brow * PB + boff;
    uint32_t bl = bh + PLANE_W;
#pragma unroll
    for (int ks = 0; ks < 8; ++ks) {
        uint32_t kadd = 32u * ks;
        uint32_t a0h[4], a1h[4], a0l[4], a1l[4];
        ldsm4(a0h, ah + kadd);
        ldsm4(a1h, ah + 16 * PB + kadd);
        ldsm4(a0l, al + kadd);
        ldsm4(a1l, al + 16 * PB + kadd);
        uint32_t b0h[4], b1h[4], b0l[4], b1l[4];
        ldsm4(b0h, bh + kadd);
        ldsm4(b1h, bh + 16 * PB + kadd);
        ldsm4(b0l, bl + kadd);
        ldsm4(b1l, bl + 16 * PB + kadd);
        // hi * hi
        mma16816(acc[0][0], a0h, b0h[0], b0h[1]);
        mma16816(acc[0][1], a0h, b0h[2], b0h[3]);
        mma16816(acc[0][2], a0h, b1h[0], b1h[1]);
        mma16816(acc[0][3], a0h, b1h[2], b1h[3]);
        mma16816(acc[1][0], a1h, b0h[0], b0h[1]);
        mma16816(acc[1][1], a1h, b0h[2], b0h[3]);
        mma16816(acc[1][2], a1h, b1h[0], b1h[1]);
        mma16816(acc[1][3], a1h, b1h[2], b1h[3]);
        // hi * lo
        mma16816(acc[0][0], a0h, b0l[0], b0l[1]);
        mma16816(acc[0][1], a0h, b0l[2], b0l[3]);
        mma16816(acc[0][2], a0h, b1l[0], b1l[1]);
        mma16816(acc[0][3], a0h, b1l[2], b1l[3]);
        mma16816(acc[1][0], a1h, b0l[0], b0l[1]);
        mma16816(acc[1][1], a1h, b0l[2], b0l[3]);
        mma16816(acc[1][2], a1h, b1l[0], b1l[1]);
        mma16816(acc[1][3], a1h, b1l[2], b1l[3]);
        // lo * hi
        mma16816(acc[0][0], a0l, b0h[0], b0h[1]);
        mma16816(acc[0][1], a0l, b0h[2], b0h[3]);
        mma16816(acc[0][2], a0l, b1h[0], b1h[1]);
        mma16816(acc[0][3], a0l, b1h[2], b1h[3]);
        mma16816(acc[1][0], a1l, b0h[0], b0h[1]);
        mma16816(acc[1][1], a1l, b0h[2], b0h[3]);
        mma16816(acc[1][2], a1l, b1h[0], b1h[1]);
        mma16816(acc[1][3], a1l, b1h[2], b1h[3]);
    }
}

// mid-layer: acc -> bias+relu -> bf16 split -> A planes; reset acc
__device__ __forceinline__ void epi_mid(float (&acc)[2][4][4], const float* bias,
                                        char* Ahi, int mb, int nb, int lane) {
    char* Alo = Ahi + PLANE_A;
    int qr = lane >> 2, qc = 2 * (lane & 3);
#pragma unroll
    for (int mt = 0; mt < 2; ++mt) {
#pragma unroll
        for (int nt = 0; nt < 4; ++nt) {
            int c = nb + 8 * nt + qc;
            float b0 = bias[c], b1 = bias[c + 1];
            int r0 = mb + 16 * mt + qr;
            float v00 = fmaxf(acc[mt][nt][0] + b0, 0.f);
            float v01 = fmaxf(acc[mt][nt][1] + b1, 0.f);
            float v10 = fmaxf(acc[mt][nt][2] + b0, 0.f);
            float v11 = fmaxf(acc[mt][nt][3] + b1, 0.f);
            uint32_t h, l;
            uint32_t o0 = (uint32_t)r0 * PB + (uint32_t)c * 2;
            split2(v00, v01, h, l);
            *(uint32_t*)(Ahi + o0) = h; *(uint32_t*)(Alo + o0) = l;
            uint32_t o1 = o0 + 8 * PB;
            split2(v10, v11, h, l);
            *(uint32_t*)(Ahi + o1) = h; *(uint32_t*)(Alo + o1) = l;
            acc[mt][nt][0] = acc[mt][nt][1] = acc[mt][nt][2] = acc[mt][nt][3] = 0.f;
        }
    }
}

// final: acc -> +bias -> fp32 staging (pitch KP floats, overlaid on A planes)
__device__ __forceinline__ void epi_stage(float (&acc)[2][4][4], const float* bias,
                                          float* stage, int mb, int nb, int lane) {
    int qr = lane >> 2, qc = 2 * (lane & 3);
#pragma unroll
    for (int mt = 0; mt < 2; ++mt) {
#pragma unroll
        for (int nt = 0; nt < 4; ++nt) {
            int c = nb + 8 * nt + qc;
            float b0 = bias[c], b1 = bias[c + 1];
            int r0 = mb + 16 * mt + qr;
            *(float2*)(stage + r0 * KP + c)       = make_float2(acc[mt][nt][0] + b0, acc[mt][nt][1] + b1);
            *(float2*)(stage + (r0 + 8) * KP + c) = make_float2(acc[mt][nt][2] + b0, acc[mt][nt][3] + b1);
        }
    }
}

// ---------------- edge kernel (64-edge tile) ----------------
__global__ void __launch_bounds__(256, 2)
edge_kernel(const char* __restrict__ w0t, const char* __restrict__ w1t, const char* __restrict__ w2t,
            const float* __restrict__ B0, const float* __restrict__ B1, const float* __restrict__ B2,
            const float* __restrict__ G,  const float* __restrict__ Bt, const int* __restrict__ eidx) {
    extern __shared__ char smem[];
    float* bs = (float*)(smem + SM_BIAS);
    int* sidx = (int*)(smem + SM_SIDX);
    char* Ahi = smem + SM_A;
    char* Wsm = smem + SM_W;
    uint32_t sb = smem_to_u32(smem);
    uint32_t Au = sb + SM_A, Wu = sb + SM_W;

    const int tid = threadIdx.x, wid = tid >> 5, lane = tid & 31;
    const int base = blockIdx.x * 64;
    const int mb = (wid >> 2) * 32, nb = (wid & 3) * 32;
    const int row = tid >> 2, cb = (tid & 3) * 32;

    if (tid < 64) {
        sidx[tid]      = eidx[base + tid];
        sidx[64 + tid] = eidx[NE + base + tid];
    }
    if (tid < 128) {
        bs[tid]       = B0[tid];
        bs[128 + tid] = B1[tid];
        bs[256 + tid] = B2[tid];
        bs[384 + tid] = G[tid];
        bs[512 + tid] = Bt[tid];
    }
    __syncthreads();

    float acc[2][4][4];
#pragma unroll
    for (int i = 0; i < 2; ++i)
#pragma unroll
        for (int j = 0; j < 4; ++j)
#pragma unroll
            for (int q = 0; q < 4; ++q) acc[i][j][q] = 0.f;

    // layer 0: K = 384 = [x[src], x[dst], e]
#pragma unroll 1
    for (int s = 0; s < 3; ++s) {
        const float* src;
        if (s == 0)      src = g_x + (size_t)sidx[row] * D;
        else if (s == 1) src = g_x + (size_t)sidx[64 + row] * D;
        else             src = g_e + (size_t)(base + row) * D;
        fill_seg(src, Ahi, row, cb);
        cpw(w0t + (size_t)s * TILE_B, Wsm, tid);
        __syncthreads();
        gemm3(Au, Wu, acc, mb, nb, lane);
        __syncthreads();
    }

    epi_mid(acc, bs, Ahi, mb, nb, lane);
    cpw(w1t, Wsm, tid);
    __syncthreads();
    gemm3(Au, Wu, acc, mb, nb, lane);
    __syncthreads();

    epi_mid(acc, bs + 128, Ahi, mb, nb, lane);
    cpw(w2t, Wsm, tid);
    __syncthreads();
    gemm3(Au, Wu, acc, mb, nb, lane);
    __syncthreads();

    float* stage = (float*)Ahi;
    epi_stage(acc, bs + 256, stage, mb, nb, lane);
    __syncthreads();

    // LN + residual + store (no scatter: node kernel gathers via CSR)
#pragma unroll 1
    for (int r = wid; r < 64; r += 8) {
        const float* st = stage + r * KP;
        int c = lane * 4;
        float4 v = *(const float4*)(st + c);
        float s1 = v.x + v.y + v.z + v.w;
        float s2 = v.x * v.x + v.y * v.y + v.z * v.z + v.w * v.w;
#pragma unroll
        for (int o = 16; o; o >>= 1) {
            s1 += __shfl_xor_sync(0xffffffffu, s1, o);
            s2 += __shfl_xor_sync(0xffffffffu, s2, o);
        }
        float mean = s1 * (1.f / D);
        float var  = s2 * (1.f / D) - mean * mean;
        float rstd = rsqrtf(var + EPSLN);
        float4 gm = *(const float4*)(bs + 384 + c);
        float4 bt = *(const float4*)(bs + 512 + c);
        float* erow = g_e + (size_t)(base + r) * D;
        float4 res = *(const float4*)(erow + c);
        float4 y;
        y.x = gm.x * (v.x - mean) * rstd + bt.x + res.x;
        y.y = gm.y * (v.y - mean) * rstd + bt.y + res.y;
        y.z = gm.z * (v.z - mean) * rstd + bt.z + res.z;
        y.w = gm.w * (v.w - mean) * rstd + bt.w + res.w;
        *(float4*)(erow + c) = y;
    }
}

// ---------------- node kernel (64-node tile, CSR gather for agg) ----------------
__global__ void __launch_bounds__(256, 2)
node_kernel(const char* __restrict__ w0t, const char* __restrict__ w1t, const char* __restrict__ w2t,
            const float* __restrict__ B0, const float* __restrict__ B1, const float* __restrict__ B2,
            const float* __restrict__ G,  const float* __restrict__ Bt) {
    extern __shared__ char smem[];
    float* bs = (float*)(smem + SM_BIAS);
    char* Ahi = smem + SM_A;
    char* Wsm = smem + SM_W;
    uint32_t sb = smem_to_u32(smem);
    uint32_t Au = sb + SM_A, Wu = sb + SM_W;

    const int tid = threadIdx.x, wid = tid >> 5, lane = tid & 31;
    const int base = blockIdx.x * 64;
    const int mb = (wid >> 2) * 32, nb = (wid & 3) * 32;
    const int row = tid >> 2, cb = (tid & 3) * 32;
    const int m = base + row;

    if (tid < 128) {
        bs[tid]       = B0[tid];
        bs[128 + tid] = B1[tid];
        bs[256 + tid] = B2[tid];
        bs[384 + tid] = G[tid];
        bs[512 + tid] = Bt[tid];
    }
    __syncthreads();

    float acc[2][4][4];
#pragma unroll
    for (int i = 0; i < 2; ++i)
#pragma unroll
        for (int j = 0; j < 4; ++j)
#pragma unroll
            for (int q = 0; q < 4; ++q) acc[i][j][q] = 0.f;

    // layer 0 segment 0: x
    fill_seg((m < NN) ? (g_x + (size_t)m * D) : (const float*)0, Ahi, row, cb);
    cpw(w0t, Wsm, tid);
    __syncthreads();
    gemm3(Au, Wu, acc, mb, nb, lane);
    __syncthreads();

    // layer 0 segment 1: agg = CSR gather-sum of this iteration's edge features
    {
        float v[32];
#pragma unroll
        for (int j = 0; j < 32; ++j) v[j] = 0.f;
        if (m < NN) {
            int p0 = g_off[m], p1 = g_off[m + 1];
#pragma unroll 1
            for (int p = p0; p < p1; ++p) {
                const float* er = g_e + (size_t)g_csr[p] * D + cb;
#pragma unroll
                for (int g = 0; g < 8; ++g) {
                    float4 t = *(const float4*)(er + g * 4);
                    v[g * 4 + 0] += t.x; v[g * 4 + 1] += t.y;
                    v[g * 4 + 2] += t.z; v[g * 4 + 3] += t.w;
                }
            }
        }
        store_seg(v, Ahi, row, cb);
        cpw(w0t + TILE_B, Wsm, tid);
        __syncthreads();
        gemm3(Au, Wu, acc, mb, nb, lane);
        __syncthreads();
    }

    epi_mid(acc, bs, Ahi, mb, nb, lane);
    cpw(w1t, Wsm, tid);
    __syncthreads();
    gemm3(Au, Wu, acc, mb, nb, lane);
    __syncthreads();

    epi_mid(acc, bs + 128, Ahi, mb, nb, lane);
    cpw(w2t, Wsm, tid);
    __syncthreads();
    gemm3(Au, Wu, acc, mb, nb, lane);
    __syncthreads();

    float* stage = (float*)Ahi;
    epi_stage(acc, bs + 256, stage, mb, nb, lane);
    __syncthreads();

#pragma unroll 1
    for (int r = wid; r < 64; r += 8) {
        int mm = base + r;
        if (mm >= NN) continue;
        const float* st = stage + r * KP;
        int c = lane * 4;
        float4 v = *(const float4*)(st + c);
        float s1 = v.x + v.y + v.z + v.w;
        float s2 = v.x * v.x + v.y * v.y + v.z * v.z + v.w * v.w;
#pragma unroll
        for (int o = 16; o; o >>= 1) {
            s1 += __shfl_xor_sync(0xffffffffu, s1, o);
            s2 += __shfl_xor_sync(0xffffffffu, s2, o);
        }
        float mean = s1 * (1.f / D);
        float var  = s2 * (1.f / D) - mean * mean;
        float rstd = rsqrtf(var + EPSLN);
        float4 gm = *(const float4*)(bs + 384 + c);
        float4 bt = *(const float4*)(bs + 512 + c);
        float* xrow = g_x + (size_t)mm * D;
        float4 res = *(const float4*)(xrow + c);
        float4 y;
        y.x = gm.x * (v.x - mean) * rstd + bt.x + res.x;
        y.y = gm.y * (v.y - mean) * rstd + bt.y + res.y;
        y.z = gm.z * (v.z - mean) * rstd + bt.z + res.z;
        y.w = gm.w * (v.w - mean) * rstd + bt.w + res.w;
        *(float4*)(xrow + c) = y;
    }
}

// ---------------- CSR build (once per launch) ----------------
__global__ void zero_k() {
    int i = blockIdx.x * blockDim.x + threadIdx.x;
    if (i < NN) g_cur[i] = 0;
}
__global__ void hist_k(const int* __restrict__ eidx) {
    int i = blockIdx.x * blockDim.x + threadIdx.x;
    if (i < NE) atomicAdd(&g_cur[eidx[NE + i]], 1);
}
// single-block inclusive scan over 1024 chunk-partials -> offsets; zeroes g_cur
__global__ void __launch_bounds__(1024, 1) scan_k() {
    __shared__ int part[1024];
    const int t = threadIdx.x;
    const int per = (NN + 1023) / 1024;
    int s = 0;
#pragma unroll 1
    for (int j = 0; j < per; ++j) {
        int idx = t * per + j;
        if (idx < NN) s += g_cur[idx];
    }
    part[t] = s;
    __syncthreads();
#pragma unroll 1
    for (int o = 1; o < 1024; o <<= 1) {
        int add = (t >= o) ? part[t - o] : 0;
        __syncthreads();
        part[t] += add;
        __syncthreads();
    }
    int base = (t == 0) ? 0 : part[t - 1];
#pragma unroll 1
    for (int j = 0; j < per; ++j) {
        int idx = t * per + j;
        if (idx < NN) {
            g_off[idx] = base;
            base += g_cur[idx];
            g_cur[idx] = 0;
        }
    }
    if (t == 1023) g_off[NN] = part[1023];
}
__global__ void fillcsr_k(const int* __restrict__ eidx) {
    int i = blockIdx.x * blockDim.x + threadIdx.x;
    if (i < NE) {
        int d = eidx[NE + i];
        int p = atomicAdd(&g_cur[d], 1);
        g_csr[g_off[d] + p] = i;
    }
}

// ---------------- weight prep: transpose + bf16 split, pitch KP ----------------
__global__ void __launch_bounds__(256, 1)
prep_w(const float* __restrict__ src, char* __restrict__ dst) {
    const int t = blockIdx.x, tid = threadIdx.x;
    const float* s = src + (size_t)t * 16384;
    char* hi = dst + (size_t)t * TILE_B;
    char* lo = hi + PLANE_W;
    const int n = tid >> 1, kb = (tid & 1) * 64;
#pragma unroll 1
    for (int g = 0; g < 8; ++g) {
        float v[8];
#pragma unroll
        for (int j = 0; j < 8; ++j) v[j] = s[(size_t)(kb + g * 8 + j) * 128 + n];
        uint4 h4, l4; cvt8(v, h4, l4);
        uint32_t o = (uint32_t)n * PB + (uint32_t)(kb + g * 8) * 2;
        *(uint4*)(hi + o) = h4; *(uint4*)(lo + o) = l4;
    }
}

// ---------------- host launch (graph-capturable) ----------------
extern "C" void kernel_launch(void* const* d_in, const int* in_sizes, int n_in,
                              void* d_out, int out_size) {
    const float* x    = (const float*)d_in[0];
    const float* ea   = (const float*)d_in[1];
    const float* eW0  = (const float*)d_in[2];
    const float* eB0  = (const float*)d_in[3];
    const float* eW1  = (const float*)d_in[4];
    const float* eB1  = (const float*)d_in[5];
    const float* eW2  = (const float*)d_in[6];
    const float* eB2  = (const float*)d_in[7];
    const float* eG   = (const float*)d_in[8];
    const float* eBt  = (const float*)d_in[9];
    const float* nW0  = (const float*)d_in[10];
    const float* nB0  = (const float*)d_in[11];
    const float* nW1  = (const float*)d_in[12];
    const float* nB1  = (const float*)d_in[13];
    const float* nW2  = (const float*)d_in[14];
    const float* nB2  = (const float*)d_in[15];
    const float* nG   = (const float*)d_in[16];
    const float* nBt  = (const float*)d_in[17];
    const int*   eidx = (const int*)d_in[18];

    float *px, *pe;
    char* pwb;
    cudaGetSymbolAddress((void**)&px,   g_x);
    cudaGetSymbolAddress((void**)&pe,   g_e);
    cudaGetSymbolAddress((void**)&pwb,  g_wb);

    cudaFuncSetAttribute(edge_kernel, cudaFuncAttributeMaxDynamicSharedMemorySize, SMEM_TOTAL);
    cudaFuncSetAttribute(node_kernel, cudaFuncAttributeMaxDynamicSharedMemorySize, SMEM_TOTAL);

    cudaMemcpyAsync(px, x,  (size_t)NN * D * sizeof(float), cudaMemcpyDeviceToDevice);
    cudaMemcpyAsync(pe, ea, (size_t)NE * D * sizeof(float), cudaMemcpyDeviceToDevice);

    // CSR build (edge_index constant across iterations)
    zero_k<<<(NN + 255) / 256, 256>>>();
    hist_k<<<(NE + 255) / 256, 256>>>(eidx);
    scan_k<<<1, 1024>>>();
    fillcsr_k<<<(NE + 255) / 256, 256>>>(eidx);

    // weight prep: 135 tiles
    prep_w<<<45, 256>>>(eW0, pwb);                                // [it*3+s]
    prep_w<<<15, 256>>>(eW1, pwb + (size_t)45  * TILE_B);
    prep_w<<<15, 256>>>(eW2, pwb + (size_t)60  * TILE_B);
    prep_w<<<30, 256>>>(nW0, pwb + (size_t)75  * TILE_B);         // [it*2+s]
    prep_w<<<15, 256>>>(nW1, pwb + (size_t)105 * TILE_B);
    prep_w<<<15, 256>>>(nW2, pwb + (size_t)120 * TILE_B);

    for (int it = 0; it < ITERS; ++it) {
        edge_kernel<<<NE / 64, 256, SMEM_TOTAL>>>(
            pwb + (size_t)(it * 3)      * TILE_B,
            pwb + (size_t)(45 + it)     * TILE_B,
            pwb + (size_t)(60 + it)     * TILE_B,
            eB0 + it * D, eB1 + it * D, eB2 + it * D,
            eG + it * D, eBt + it * D, eidx);
        node_kernel<<<(NN + 63) / 64, 256, SMEM_TOTAL>>>(
            pwb + (size_t)(75 + it * 2) * TILE_B,
            pwb + (size_t)(105 + it)    * TILE_B,
            pwb + (size_t)(120 + it)    * TILE_B,
            nB0 + it * D, nB1 + it * D, nB2 + it * D,
            nG + it * D, nBt + it * D);
    }

    cudaMemcpyAsync(d_out, px, (size_t)NN * D * sizeof(float), cudaMemcpyDeviceToDevice);
    cudaMemcpyAsync((float*)d_out + (size_t)NN * D, pe,
                    (size_t)NE * D * sizeof(float), cudaMemcpyDeviceToDevice);
}

// round 15
// speedup vs baseline: 2.2236x; 1.0699x over previous
#include <cuda_runtime.h>
#include <cuda_bf16.h>
#include <cstdint>

#define NN 20000
#define NE 80000
#define D  128
#define ITERS 15
#define EPSLN 1e-5f

#define KP  136          // bf16 pitch (272B rows: conflict-free ldmatrix, 16B aligned)
#define PB  272
#define PLANE_A (64 * PB)    // 17408 B per A bf16 plane (64-row tile)
#define PLANE_W (128 * PB)   // 34816 B per W bf16 plane

// ---------------- persistent device state ----------------
__device__ float g_x[NN * D];
__device__ float g_e[NE * D];
__device__ float g_Pa[NN * D];   // x @ eW0[:,0:128 rows of K]   (src term)
__device__ float g_Pb[NN * D];   // x @ eW0[128:256]             (dst term)
// CSR of edges grouped by destination node (built once per launch)
__device__ int g_off[NN + 1];
__device__ int g_cur[NN];
__device__ int g_csr[NE];
// 135 prepped weight tiles: hi plane [128 n][KP bf16] + lo plane
#define TILE_B 69632
#define NTILES 135
__device__ __align__(16) char g_wb[(size_t)NTILES * TILE_B];

// ---------------- smem layout (bytes) ----------------
#define SM_BIAS 0        // 5*128 floats: B0,B1,B2,G,Beta
#define SM_SIDX 2560     // 128 ints (edge: src[64], dst[64])
#define SM_A    3584     // Ahi, Alo (2*17408) ; doubles as fp32 staging 64x136
#define SM_W    (SM_A + 2 * PLANE_A)      // Whi, Wlo
#define SMEM_TOTAL (SM_W + 2 * PLANE_W)   // 108032  (x2 CTAs = 216KB < 227KB)

// ---------------- helpers ----------------
__device__ __forceinline__ uint32_t smem_to_u32(const void* p) {
    uint32_t a;
    asm("{ .reg .u64 t; cvta.to.shared.u64 t, %1; cvt.u32.u64 %0, t; }" : "=r"(a) : "l"(p));
    return a;
}
__device__ __forceinline__ void ldsm4(uint32_t* r, uint32_t addr) {
    asm volatile("ldmatrix.sync.aligned.m8n8.x4.shared.b16 {%0,%1,%2,%3}, [%4];"
        : "=r"(r[0]), "=r"(r[1]), "=r"(r[2]), "=r"(r[3]) : "r"(addr));
}
__device__ __forceinline__ void mma16816(float* c, const uint32_t* a, uint32_t b0, uint32_t b1) {
    asm volatile("mma.sync.aligned.m16n8k16.row.col.f32.bf16.bf16.f32 "
        "{%0,%1,%2,%3}, {%4,%5,%6,%7}, {%8,%9}, {%0,%1,%2,%3};"
        : "+f"(c[0]), "+f"(c[1]), "+f"(c[2]), "+f"(c[3])
        : "r"(a[0]), "r"(a[1]), "r"(a[2]), "r"(a[3]), "r"(b0), "r"(b1));
}

__device__ __forceinline__ void cvt8(const float* v, uint4& h4, uint4& l4) {
    uint32_t h[4], l[4];
#pragma unroll
    for (int i = 0; i < 4; ++i) {
        __nv_bfloat16 a0 = __float2bfloat16(v[2 * i]);
        __nv_bfloat16 a1 = __float2bfloat16(v[2 * i + 1]);
        float r0 = v[2 * i]     - __bfloat162float(a0);
        float r1 = v[2 * i + 1] - __bfloat162float(a1);
        h[i] = (uint32_t)__bfloat16_as_ushort(a0) | ((uint32_t)__bfloat16_as_ushort(a1) << 16);
        l[i] = (uint32_t)__bfloat16_as_ushort(__float2bfloat16(r0)) |
               ((uint32_t)__bfloat16_as_ushort(__float2bfloat16(r1)) << 16);
    }
    h4 = make_uint4(h[0], h[1], h[2], h[3]);
    l4 = make_uint4(l[0], l[1], l[2], l[3]);
}
__device__ __forceinline__ void split2(float x, float y, uint32_t& h, uint32_t& l) {
    __nv_bfloat16 hx = __float2bfloat16(x), hy = __float2bfloat16(y);
    float rx = x - __bfloat162float(hx), ry = y - __bfloat162float(hy);
    h = (uint32_t)__bfloat16_as_ushort(hx) | ((uint32_t)__bfloat16_as_ushort(hy) << 16);
    l = (uint32_t)__bfloat16_as_ushort(__float2bfloat16(rx)) |
        ((uint32_t)__bfloat16_as_ushort(__float2bfloat16(ry)) << 16);
}

// write 32 fp32 values into the A hi/lo planes at (row, cb)
__device__ __forceinline__ void store_seg(const float* v, char* Ahi, int row, int cb) {
    char* Alo = Ahi + PLANE_A;
#pragma unroll
    for (int g = 0; g < 4; ++g) {
        uint4 h4, l4; cvt8(v + g * 8, h4, l4);
        uint32_t o = (uint32_t)row * PB + (uint32_t)(cb + g * 8) * 2;
        *(uint4*)(Ahi + o) = h4; *(uint4*)(Alo + o) = l4;
    }
}

// gather one 32-col quarter-row into A hi/lo planes (64-row tile, 4 thr/row)
__device__ __forceinline__ void fill_seg(const float* srcrow, char* Ahi, int row, int cb) {
    if (srcrow) {
        float v[32];
#pragma unroll
        for (int g = 0; g < 8; ++g) *(float4*)(v + g * 4) = *(const float4*)(srcrow + cb + g * 4);
        store_seg(v, Ahi, row, cb);
    } else {
        char* Alo = Ahi + PLANE_A;
        uint4 z = make_uint4(0, 0, 0, 0);
#pragma unroll
        for (int g = 0; g < 4; ++g) {
            uint32_t o = (uint32_t)row * PB + (uint32_t)(cb + g * 8) * 2;
            *(uint4*)(Ahi + o) = z; *(uint4*)(Alo + o) = z;
        }
    }
}

// copy one prepped weight tile (hi+lo, 68KB) into smem
__device__ __forceinline__ void cpw(const char* src, char* dst, int tid) {
    const float4* s = (const float4*)src;
    float4* d = (float4*)dst;
#pragma unroll
    for (int i = 0; i < 17; ++i) {
        int idx = tid + i * 256;
        if (idx < TILE_B / 16) d[idx] = s[idx];
    }
}

#define ZERO_ACC(acc) do {                       \
    _Pragma("unroll")                            \
    for (int _i = 0; _i < 2; ++_i)               \
        _Pragma("unroll")                        \
        for (int _j = 0; _j < 4; ++_j)           \
            _Pragma("unroll")                    \
            for (int _q = 0; _q < 4; ++_q) (acc)[_i][_j][_q] = 0.f; \
} while (0)

// merged 3-term bf16-split GEMM: acc += Ahi*Whi + Ahi*Wlo + Alo*Whi
// warp tile m32 x n32 ; warp grid 2(m) x 4(n)
__device__ __forceinline__ void gemm3(uint32_t Au, uint32_t Wu,
                                      float (&acc)[2][4][4], int mb, int nb, int lane) {
    uint32_t arow = (uint32_t)(mb + (lane & 15));
    uint32_t aoff = (lane & 16) ? 16u : 0u;
    uint32_t ah = Au + arow * PB + aoff;
    uint32_t al = ah + PLANE_A;
    uint32_t brow = (uint32_t)(nb + (lane & 7) + ((lane & 16) ? 8 : 0));
    uint32_t boff = (lane & 8) ? 16u : 0u;
    uint32_t bh = Wu + brow * PB + boff;
    uint32_t bl = bh + PLANE_W;
#pragma unroll
    for (int ks = 0; ks < 8; ++ks) {
        uint32_t kadd = 32u * ks;
        uint32_t a0h[4], a1h[4], a0l[4], a1l[4];
        ldsm4(a0h, ah + kadd);
        ldsm4(a1h, ah + 16 * PB + kadd);
        ldsm4(a0l, al + kadd);
        ldsm4(a1l, al + 16 * PB + kadd);
        uint32_t b0h[4], b1h[4], b0l[4], b1l[4];
        ldsm4(b0h, bh + kadd);
        ldsm4(b1h, bh + 16 * PB + kadd);
        ldsm4(b0l, bl + kadd);
        ldsm4(b1l, bl + 16 * PB + kadd);
        // hi * hi
        mma16816(acc[0][0], a0h, b0h[0], b0h[1]);
        mma16816(acc[0][1], a0h, b0h[2], b0h[3]);
        mma16816(acc[0][2], a0h, b1h[0], b1h[1]);
        mma16816(acc[0][3], a0h, b1h[2], b1h[3]);
        mma16816(acc[1][0], a1h, b0h[0], b0h[1]);
        mma16816(acc[1][1], a1h, b0h[2], b0h[3]);
        mma16816(acc[1][2], a1h, b1h[0], b1h[1]);
        mma16816(acc[1][3], a1h, b1h[2], b1h[3]);
        // hi * lo
        mma16816(acc[0][0], a0h, b0l[0], b0l[1]);
        mma16816(acc[0][1], a0h, b0l[2], b0l[3]);
        mma16816(acc[0][2], a0h, b1l[0], b1l[1]);
        mma16816(acc[0][3], a0h, b1l[2], b1l[3]);
        mma16816(acc[1][0], a1h, b0l[0], b0l[1]);
        mma16816(acc[1][1], a1h, b0l[2], b0l[3]);
        mma16816(acc[1][2], a1h, b1l[0], b1l[1]);
        mma16816(acc[1][3], a1h, b1l[2], b1l[3]);
        // lo * hi
        mma16816(acc[0][0], a0l, b0h[0], b0h[1]);
        mma16816(acc[0][1], a0l, b0h[2], b0h[3]);
        mma16816(acc[0][2], a0l, b1h[0], b1h[1]);
        mma16816(acc[0][3], a0l, b1h[2], b1h[3]);
        mma16816(acc[1][0], a1l, b0h[0], b0h[1]);
        mma16816(acc[1][1], a1l, b0h[2], b0h[3]);
        mma16816(acc[1][2], a1l, b1h[0], b1h[1]);
        mma16816(acc[1][3], a1l, b1h[2], b1h[3]);
    }
}

// mid-layer: acc -> bias+relu -> bf16 split -> A planes; reset acc
__device__ __forceinline__ void epi_mid(float (&acc)[2][4][4], const float* bias,
                                        char* Ahi, int mb, int nb, int lane) {
    char* Alo = Ahi + PLANE_A;
    int qr = lane >> 2, qc = 2 * (lane & 3);
#pragma unroll
    for (int mt = 0; mt < 2; ++mt) {
#pragma unroll
        for (int nt = 0; nt < 4; ++nt) {
            int c = nb + 8 * nt + qc;
            float b0 = bias[c], b1 = bias[c + 1];
            int r0 = mb + 16 * mt + qr;
            float v00 = fmaxf(acc[mt][nt][0] + b0, 0.f);
            float v01 = fmaxf(acc[mt][nt][1] + b1, 0.f);
            float v10 = fmaxf(acc[mt][nt][2] + b0, 0.f);
            float v11 = fmaxf(acc[mt][nt][3] + b1, 0.f);
            uint32_t h, l;
            uint32_t o0 = (uint32_t)r0 * PB + (uint32_t)c * 2;
            split2(v00, v01, h, l);
            *(uint32_t*)(Ahi + o0) = h; *(uint32_t*)(Alo + o0) = l;
            uint32_t o1 = o0 + 8 * PB;
            split2(v10, v11, h, l);
            *(uint32_t*)(Ahi + o1) = h; *(uint32_t*)(Alo + o1) = l;
            acc[mt][nt][0] = acc[mt][nt][1] = acc[mt][nt][2] = acc[mt][nt][3] = 0.f;
        }
    }
}

// final: acc -> +bias -> fp32 staging (pitch KP floats, overlaid on A planes)
__device__ __forceinline__ void epi_stage(float (&acc)[2][4][4], const float* bias,
                                          float* stage, int mb, int nb, int lane) {
    int qr = lane >> 2, qc = 2 * (lane & 3);
#pragma unroll
    for (int mt = 0; mt < 2; ++mt) {
#pragma unroll
        for (int nt = 0; nt < 4; ++nt) {
            int c = nb + 8 * nt + qc;
            float b0 = bias[c], b1 = bias[c + 1];
            int r0 = mb + 16 * mt + qr;
            *(float2*)(stage + r0 * KP + c)       = make_float2(acc[mt][nt][0] + b0, acc[mt][nt][1] + b1);
            *(float2*)(stage + (r0 + 8) * KP + c) = make_float2(acc[mt][nt][2] + b0, acc[mt][nt][3] + b1);
        }
    }
}

// write acc fragments directly to a [NN, D] fp32 global (P buffers)
__device__ __forceinline__ void write_P(float (&acc)[2][4][4], float* dst,
                                        int base, int mb, int nb, int lane) {
    int qr = lane >> 2, qc = 2 * (lane & 3);
#pragma unroll
    for (int mt = 0; mt < 2; ++mt) {
#pragma unroll
        for (int nt = 0; nt < 4; ++nt) {
            int c = nb + 8 * nt + qc;
            int m0 = base + mb + 16 * mt + qr;
            if (m0 < NN)
                *(float2*)(dst + (size_t)m0 * D + c) = make_float2(acc[mt][nt][0], acc[mt][nt][1]);
            if (m0 + 8 < NN)
                *(float2*)(dst + (size_t)(m0 + 8) * D + c) = make_float2(acc[mt][nt][2], acc[mt][nt][3]);
        }
    }
}

// ---------------- edge kernel (64-edge tile; layer0 = Pa[src]+Pb[dst] + e@W0c) ----------------
__global__ void __launch_bounds__(256, 2)
edge_kernel(const char* __restrict__ w0c, const char* __restrict__ w1t, const char* __restrict__ w2t,
            const float* __restrict__ B0, const float* __restrict__ B1, const float* __restrict__ B2,
            const float* __restrict__ G,  const float* __restrict__ Bt, const int* __restrict__ eidx) {
    extern __shared__ char smem[];
    float* bs = (float*)(smem + SM_BIAS);
    int* sidx = (int*)(smem + SM_SIDX);
    char* Ahi = smem + SM_A;
    char* Wsm = smem + SM_W;
    uint32_t sb = smem_to_u32(smem);
    uint32_t Au = sb + SM_A, Wu = sb + SM_W;
    float* stage = (float*)Ahi;

    const int tid = threadIdx.x, wid = tid >> 5, lane = tid & 31;
    const int base = blockIdx.x * 64;
    const int mb = (wid >> 2) * 32, nb = (wid & 3) * 32;
    const int row = tid >> 2, cb = (tid & 3) * 32;

    if (tid < 64) {
        sidx[tid]      = eidx[base + tid];
        sidx[64 + tid] = eidx[NE + base + tid];
    }
    if (tid < 128) {
        bs[tid]       = B0[tid];
        bs[128 + tid] = B1[tid];
        bs[256 + tid] = B2[tid];
        bs[384 + tid] = G[tid];
        bs[512 + tid] = Bt[tid];
    }
    __syncthreads();

    // stage <- Pa[src] + Pb[dst]   (fp32 gather-add; kicks off W0c copy too)
    {
        const float* pa = g_Pa + (size_t)sidx[row] * D + cb;
        const float* pb = g_Pb + (size_t)sidx[64 + row] * D + cb;
        float* st = stage + row * KP + cb;
#pragma unroll
        for (int g = 0; g < 8; ++g) {
            float4 ta = *(const float4*)(pa + g * 4);
            float4 tb = *(const float4*)(pb + g * 4);
            *(float4*)(st + g * 4) = make_float4(ta.x + tb.x, ta.y + tb.y, ta.z + tb.z, ta.w + tb.w);
        }
    }
    __syncthreads();

    // acc <- stage (fragment-wise init)
    float acc[2][4][4];
    {
        int qr = lane >> 2, qc = 2 * (lane & 3);
#pragma unroll
        for (int mt = 0; mt < 2; ++mt) {
#pragma unroll
            for (int nt = 0; nt < 4; ++nt) {
                int c = nb + 8 * nt + qc;
                int r0 = mb + 16 * mt + qr;
                acc[mt][nt][0] = stage[r0 * KP + c];
                acc[mt][nt][1] = stage[r0 * KP + c + 1];
                acc[mt][nt][2] = stage[(r0 + 8) * KP + c];
                acc[mt][nt][3] = stage[(r0 + 8) * KP + c + 1];
            }
        }
    }
    __syncthreads();

    // layer 0 remainder: e @ W0c
    fill_seg(g_e + (size_t)(base + row) * D, Ahi, row, cb);
    cpw(w0c, Wsm, tid);
    __syncthreads();
    gemm3(Au, Wu, acc, mb, nb, lane);
    __syncthreads();

    epi_mid(acc, bs, Ahi, mb, nb, lane);
    cpw(w1t, Wsm, tid);
    __syncthreads();
    gemm3(Au, Wu, acc, mb, nb, lane);
    __syncthreads();

    epi_mid(acc, bs + 128, Ahi, mb, nb, lane);
    cpw(w2t, Wsm, tid);
    __syncthreads();
    gemm3(Au, Wu, acc, mb, nb, lane);
    __syncthreads();

    epi_stage(acc, bs + 256, stage, mb, nb, lane);
    __syncthreads();

    // LN + residual + store
#pragma unroll 1
    for (int r = wid; r < 64; r += 8) {
        const float* st = stage + r * KP;
        int c = lane * 4;
        float4 v = *(const float4*)(st + c);
        float s1 = v.x + v.y + v.z + v.w;
        float s2 = v.x * v.x + v.y * v.y + v.z * v.z + v.w * v.w;
#pragma unroll
        for (int o = 16; o; o >>= 1) {
            s1 += __shfl_xor_sync(0xffffffffu, s1, o);
            s2 += __shfl_xor_sync(0xffffffffu, s2, o);
        }
        float mean = s1 * (1.f / D);
        float var  = s2 * (1.f / D) - mean * mean;
        float rstd = rsqrtf(var + EPSLN);
        float4 gm = *(const float4*)(bs + 384 + c);
        float4 bt = *(const float4*)(bs + 512 + c);
        float* erow = g_e + (size_t)(base + r) * D;
        float4 res = *(const float4*)(erow + c);
        float4 y;
        y.x = gm.x * (v.x - mean) * rstd + bt.x + res.x;
        y.y = gm.y * (v.y - mean) * rstd + bt.y + res.y;
        y.z = gm.z * (v.z - mean) * rstd + bt.z + res.z;
        y.w = gm.w * (v.w - mean) * rstd + bt.w + res.w;
        *(float4*)(erow + c) = y;
    }
}

// ---------------- node kernel (64-node tile, CSR gather; fused next-iter P) ----------------
__global__ void __launch_bounds__(256, 2)
node_kernel(const char* __restrict__ w0t, const char* __restrict__ w1t, const char* __restrict__ w2t,
            const float* __restrict__ B0, const float* __restrict__ B1, const float* __restrict__ B2,
            const float* __restrict__ G,  const float* __restrict__ Bt,
            const char* __restrict__ wea, const char* __restrict__ web, int has_next) {
    extern __shared__ char smem[];
    float* bs = (float*)(smem + SM_BIAS);
    char* Ahi = smem + SM_A;
    char* Wsm = smem + SM_W;
    uint32_t sb = smem_to_u32(smem);
    uint32_t Au = sb + SM_A, Wu = sb + SM_W;
    float* stage = (float*)Ahi;

    const int tid = threadIdx.x, wid = tid >> 5, lane = tid & 31;
    const int base = blockIdx.x * 64;
    const int mb = (wid >> 2) * 32, nb = (wid & 3) * 32;
    const int row = tid >> 2, cb = (tid & 3) * 32;
    const int m = base + row;

    if (tid < 128) {
        bs[tid]       = B0[tid];
        bs[128 + tid] = B1[tid];
        bs[256 + tid] = B2[tid];
        bs[384 + tid] = G[tid];
        bs[512 + tid] = Bt[tid];
    }
    __syncthreads();

    float acc[2][4][4];
    ZERO_ACC(acc);

    // layer 0 segment 0: x
    fill_seg((m < NN) ? (g_x + (size_t)m * D) : (const float*)0, Ahi, row, cb);
    cpw(w0t, Wsm, tid);
    __syncthreads();
    gemm3(Au, Wu, acc, mb, nb, lane);
    __syncthreads();

    // layer 0 segment 1: agg = CSR gather-sum of this iteration's edge features
    {
        float v[32];
#pragma unroll
        for (int j = 0; j < 32; ++j) v[j] = 0.f;
        if (m < NN) {
            int p0 = g_off[m], p1 = g_off[m + 1];
#pragma unroll 1
            for (int p = p0; p < p1; ++p) {
                const float* er = g_e + (size_t)g_csr[p] * D + cb;
#pragma unroll
                for (int g = 0; g < 8; ++g) {
                    float4 t = *(const float4*)(er + g * 4);
                    v[g * 4 + 0] += t.x; v[g * 4 + 1] += t.y;
                    v[g * 4 + 2] += t.z; v[g * 4 + 3] += t.w;
                }
            }
        }
        store_seg(v, Ahi, row, cb);
        cpw(w0t + TILE_B, Wsm, tid);
        __syncthreads();
        gemm3(Au, Wu, acc, mb, nb, lane);
        __syncthreads();
    }

    epi_mid(acc, bs, Ahi, mb, nb, lane);
    cpw(w1t, Wsm, tid);
    __syncthreads();
    gemm3(Au, Wu, acc, mb, nb, lane);
    __syncthreads();

    epi_mid(acc, bs + 128, Ahi, mb, nb, lane);
    cpw(w2t, Wsm, tid);
    __syncthreads();
    gemm3(Au, Wu, acc, mb, nb, lane);
    __syncthreads();

    epi_stage(acc, bs + 256, stage, mb, nb, lane);
    __syncthreads();

    // LN + residual -> new x; also keep new x in stage for the fused P GEMMs
#pragma unroll 1
    for (int r = wid; r < 64; r += 8) {
        int mm = base + r;
        float* st = stage + r * KP;
        int c = lane * 4;
        float4 v = *(const float4*)(st + c);
        float s1 = v.x + v.y + v.z + v.w;
        float s2 = v.x * v.x + v.y * v.y + v.z * v.z + v.w * v.w;
#pragma unroll
        for (int o = 16; o; o >>= 1) {
            s1 += __shfl_xor_sync(0xffffffffu, s1, o);
            s2 += __shfl_xor_sync(0xffffffffu, s2, o);
        }
        float mean = s1 * (1.f / D);
        float var  = s2 * (1.f / D) - mean * mean;
        float rstd = rsqrtf(var + EPSLN);
        float4 gm = *(const float4*)(bs + 384 + c);
        float4 bt = *(const float4*)(bs + 512 + c);
        if (mm < NN) {
            float* xrow = g_x + (size_t)mm * D;
            float4 res = *(const float4*)(xrow + c);
            float4 y;
            y.x = gm.x * (v.x - mean) * rstd + bt.x + res.x;
            y.y = gm.y * (v.y - mean) * rstd + bt.y + res.y;
            y.z = gm.z * (v.z - mean) * rstd + bt.z + res.z;
            y.w = gm.w * (v.w - mean) * rstd + bt.w + res.w;
            *(float4*)(xrow + c) = y;
            *(float4*)(st + c) = y;
        }
    }

    if (!has_next) return;

    // ---- fused: P = new_x @ eW0{a,b} for the NEXT iteration ----
    __syncthreads();
    float v[32];
#pragma unroll
    for (int g = 0; g < 8; ++g) *(float4*)(v + g * 4) = *(const float4*)(stage + row * KP + cb + g * 4);
    __syncthreads();
    store_seg(v, Ahi, row, cb);      // A planes <- new x (overwrites stage)
    cpw(wea, Wsm, tid);
    __syncthreads();
    ZERO_ACC(acc);
    gemm3(Au, Wu, acc, mb, nb, lane);
    __syncthreads();                 // Wsm reuse barrier
    write_P(acc, g_Pa, base, mb, nb, lane);
    cpw(web, Wsm, tid);
    __syncthreads();
    ZERO_ACC(acc);
    gemm3(Au, Wu, acc, mb, nb, lane);
    write_P(acc, g_Pb, base, mb, nb, lane);
}

// ---------------- P seed for iteration 0 ----------------
__global__ void __launch_bounds__(256, 2)
p0_kernel(const char* __restrict__ wea, const char* __restrict__ web) {
    extern __shared__ char smem[];
    char* Ahi = smem + SM_A;
    char* Wsm = smem + SM_W;
    uint32_t sb = smem_to_u32(smem);
    uint32_t Au = sb + SM_A, Wu = sb + SM_W;

    const int tid = threadIdx.x, wid = tid >> 5, lane = tid & 31;
    const int base = blockIdx.x * 64;
    const int mb = (wid >> 2) * 32, nb = (wid & 3) * 32;
    const int row = tid >> 2, cb = (tid & 3) * 32;
    const int m = base + row;

    fill_seg((m < NN) ? (g_x + (size_t)m * D) : (const float*)0, Ahi, row, cb);
    cpw(wea, Wsm, tid);
    __syncthreads();
    float acc[2][4][4];
    ZERO_ACC(acc);
    gemm3(Au, Wu, acc, mb, nb, lane);
    __syncthreads();
    write_P(acc, g_Pa, base, mb, nb, lane);
    cpw(web, Wsm, tid);
    __syncthreads();
    ZERO_ACC(acc);
    gemm3(Au, Wu, acc, mb, nb, lane);
    write_P(acc, g_Pb, base, mb, nb, lane);
}

// ---------------- CSR build (once per launch) ----------------
__global__ void zero_k() {
    int i = blockIdx.x * blockDim.x + threadIdx.x;
    if (i < NN) g_cur[i] = 0;
}
__global__ void hist_k(const int* __restrict__ eidx) {
    int i = blockIdx.x * blockDim.x + threadIdx.x;
    if (i < NE) atomicAdd(&g_cur[eidx[NE + i]], 1);
}
__global__ void __launch_bounds__(1024, 1) scan_k() {
    __shared__ int part[1024];
    const int t = threadIdx.x;
    const int per = (NN + 1023) / 1024;
    int s = 0;
#pragma unroll 1
    for (int j = 0; j < per; ++j) {
        int idx = t * per + j;
        if (idx < NN) s += g_cur[idx];
    }
    part[t] = s;
    __syncthreads();
#pragma unroll 1
    for (int o = 1; o < 1024; o <<= 1) {
        int add = (t >= o) ? part[t - o] : 0;
        __syncthreads();
        part[t] += add;
        __syncthreads();
    }
    int base = (t == 0) ? 0 : part[t - 1];
#pragma unroll 1
    for (int j = 0; j < per; ++j) {
        int idx = t * per + j;
        if (idx < NN) {
            g_off[idx] = base;
            base += g_cur[idx];
            g_cur[idx] = 0;
        }
    }
    if (t == 1023) g_off[NN] = part[1023];
}
__global__ void fillcsr_k(const int* __restrict__ eidx) {
    int i = blockIdx.x * blockDim.x + threadIdx.x;
    if (i < NE) {
        int d = eidx[NE + i];
        int p = atomicAdd(&g_cur[d], 1);
        g_csr[g_off[d] + p] = i;
    }
}

// ---------------- weight prep: transpose + bf16 split, pitch KP ----------------
__global__ void __launch_bounds__(256, 1)
prep_w(const float* __restrict__ src, char* __restrict__ dst) {
    const int t = blockIdx.x, tid = threadIdx.x;
    const float* s = src + (size_t)t * 16384;
    char* hi = dst + (size_t)t * TILE_B;
    char* lo = hi + PLANE_W;
    const int n = tid >> 1, kb = (tid & 1) * 64;
#pragma unroll 1
    for (int g = 0; g < 8; ++g) {
        float v[8];
#pragma unroll
        for (int j = 0; j < 8; ++j) v[j] = s[(size_t)(kb + g * 8 + j) * 128 + n];
        uint4 h4, l4; cvt8(v, h4, l4);
        uint32_t o = (uint32_t)n * PB + (uint32_t)(kb + g * 8) * 2;
        *(uint4*)(hi + o) = h4; *(uint4*)(lo + o) = l4;
    }
}

// ---------------- host launch (graph-capturable) ----------------
extern "C" void kernel_launch(void* const* d_in, const int* in_sizes, int n_in,
                              void* d_out, int out_size) {
    const float* x    = (const float*)d_in[0];
    const float* ea   = (const float*)d_in[1];
    const float* eW0  = (const float*)d_in[2];
    const float* eB0  = (const float*)d_in[3];
    const float* eW1  = (const float*)d_in[4];
    const float* eB1  = (const float*)d_in[5];
    const float* eW2  = (const float*)d_in[6];
    const float* eB2  = (const float*)d_in[7];
    const float* eG   = (const float*)d_in[8];
    const float* eBt  = (const float*)d_in[9];
    const float* nW0  = (const float*)d_in[10];
    const float* nB0  = (const float*)d_in[11];
    const float* nW1  = (const float*)d_in[12];
    const float* nB1  = (const float*)d_in[13];
    const float* nW2  = (const float*)d_in[14];
    const float* nB2  = (const float*)d_in[15];
    const float* nG   = (const float*)d_in[16];
    const float* nBt  = (const float*)d_in[17];
    const int*   eidx = (const int*)d_in[18];

    float *px, *pe;
    char* pwb;
    cudaGetSymbolAddress((void**)&px,   g_x);
    cudaGetSymbolAddress((void**)&pe,   g_e);
    cudaGetSymbolAddress((void**)&pwb,  g_wb);

    cudaFuncSetAttribute(edge_kernel, cudaFuncAttributeMaxDynamicSharedMemorySize, SMEM_TOTAL);
    cudaFuncSetAttribute(node_kernel, cudaFuncAttributeMaxDynamicSharedMemorySize, SMEM_TOTAL);
    cudaFuncSetAttribute(p0_kernel,   cudaFuncAttributeMaxDynamicSharedMemorySize, SMEM_TOTAL);

    cudaMemcpyAsync(px, x,  (size_t)NN * D * sizeof(float), cudaMemcpyDeviceToDevice);
    cudaMemcpyAsync(pe, ea, (size_t)NE * D * sizeof(float), cudaMemcpyDeviceToDevice);

    // CSR build (edge_index constant across iterations)
    zero_k<<<(NN + 255) / 256, 256>>>();
    hist_k<<<(NE + 255) / 256, 256>>>(eidx);
    scan_k<<<1, 1024>>>();
    fillcsr_k<<<(NE + 255) / 256, 256>>>(eidx);

    // weight prep: 135 tiles
    prep_w<<<45, 256>>>(eW0, pwb);                                // [it*3+s] s=0:a 1:b 2:c
    prep_w<<<15, 256>>>(eW1, pwb + (size_t)45  * TILE_B);
    prep_w<<<15, 256>>>(eW2, pwb + (size_t)60  * TILE_B);
    prep_w<<<30, 256>>>(nW0, pwb + (size_t)75  * TILE_B);         // [it*2+s]
    prep_w<<<15, 256>>>(nW1, pwb + (size_t)105 * TILE_B);
    prep_w<<<15, 256>>>(nW2, pwb + (size_t)120 * TILE_B);

    const int NB = (NN + 63) / 64;   // 313
    // seed P for iteration 0
    p0_kernel<<<NB, 256, SMEM_TOTAL>>>(pwb, pwb + TILE_B);

    for (int it = 0; it < ITERS; ++it) {
        edge_kernel<<<NE / 64, 256, SMEM_TOTAL>>>(
            pwb + (size_t)(it * 3 + 2)  * TILE_B,
            pwb + (size_t)(45 + it)     * TILE_B,
            pwb + (size_t)(60 + it)     * TILE_B,
            eB0 + it * D, eB1 + it * D, eB2 + it * D,
            eG + it * D, eBt + it * D, eidx);
        node_kernel<<<NB, 256, SMEM_TOTAL>>>(
            pwb + (size_t)(75 + it * 2) * TILE_B,
            pwb + (size_t)(105 + it)    * TILE_B,
            pwb + (size_t)(120 + it)    * TILE_B,
            nB0 + it * D, nB1 + it * D, nB2 + it * D,
            nG + it * D, nBt + it * D,
            pwb + (size_t)((it + 1) * 3)     * TILE_B,
            pwb + (size_t)((it + 1) * 3 + 1) * TILE_B,
            (it < ITERS - 1) ? 1 : 0);
    }

    cudaMemcpyAsync(d_out, px, (size_t)NN * D * sizeof(float), cudaMemcpyDeviceToDevice);
    cudaMemcpyAsync((float*)d_out + (size_t)NN * D, pe,
                    (size_t)NE * D * sizeof(float), cudaMemcpyDeviceToDevice);
}

// round 16
// speedup vs baseline: 2.3556x; 1.0594x over previous
#include <cuda_runtime.h>
#include <cuda_bf16.h>
#include <cstdint>

#define NN 20000
#define NE 80000
#define D  128
#define ITERS 15
#define EPSLN 1e-5f

#define KP  136          // bf16 pitch (272B rows: conflict-free ldmatrix, 16B aligned)
#define PB  272
#define PLANE_A (64 * PB)    // 17408 B per A bf16 plane (64-row tile)
#define HI_B 34816           // hi plane bytes (128 x 272)
#define LO_OFF 34816         // lo plane offset within a prepped tile
// prepped tile: hi plane [n][k] pitch-272 (34816B) + lo plane in fragment blocks
// lo block (n8, ks): 256B at (n8*8+ks)*256 ; lane l holds uint2 {pair(k=2(l&3)+{0,1}), +8}
#define TILE_B 69632
#define NTILES 135

// ---------------- persistent device state ----------------
__device__ float g_x[NN * D];
__device__ float g_e[NE * D];
__device__ float g_Pa[NN * D];   // x @ eW0a   (src term)
__device__ float g_Pb[NN * D];   // x @ eW0b   (dst term)
__device__ int g_off[NN + 1];
__device__ int g_cur[NN];
__device__ int g_csr[NE];
__device__ __align__(16) char g_wb[(size_t)NTILES * TILE_B];

// ---------------- smem layout (bytes): 73216 -> 3 CTAs/SM ----------------
#define SM_BIAS 0        // 5*128 floats
#define SM_SIDX 2560     // 128 ints
#define SM_A    3584     // Ahi, Alo (2*17408); doubles as fp32 staging 64x136
#define SM_W    (SM_A + 2 * PLANE_A)      // 38400: Whi only
#define SMEM_TOTAL (SM_W + HI_B)          // 73216

// ---------------- helpers ----------------
__device__ __forceinline__ uint32_t smem_to_u32(const void* p) {
    uint32_t a;
    asm("{ .reg .u64 t; cvta.to.shared.u64 t, %1; cvt.u32.u64 %0, t; }" : "=r"(a) : "l"(p));
    return a;
}
__device__ __forceinline__ void ldsm4(uint32_t* r, uint32_t addr) {
    asm volatile("ldmatrix.sync.aligned.m8n8.x4.shared.b16 {%0,%1,%2,%3}, [%4];"
        : "=r"(r[0]), "=r"(r[1]), "=r"(r[2]), "=r"(r[3]) : "r"(addr));
}
__device__ __forceinline__ void mma16816(float* c, const uint32_t* a, uint32_t b0, uint32_t b1) {
    asm volatile("mma.sync.aligned.m16n8k16.row.col.f32.bf16.bf16.f32 "
        "{%0,%1,%2,%3}, {%4,%5,%6,%7}, {%8,%9}, {%0,%1,%2,%3};"
        : "+f"(c[0]), "+f"(c[1]), "+f"(c[2]), "+f"(c[3])
        : "r"(a[0]), "r"(a[1]), "r"(a[2]), "r"(a[3]), "r"(b0), "r"(b1));
}

__device__ __forceinline__ void cvt8(const float* v, uint4& h4, uint4& l4) {
    uint32_t h[4], l[4];
#pragma unroll
    for (int i = 0; i < 4; ++i) {
        __nv_bfloat16 a0 = __float2bfloat16(v[2 * i]);
        __nv_bfloat16 a1 = __float2bfloat16(v[2 * i + 1]);
        float r0 = v[2 * i]     - __bfloat162float(a0);
        float r1 = v[2 * i + 1] - __bfloat162float(a1);
        h[i] = (uint32_t)__bfloat16_as_ushort(a0) | ((uint32_t)__bfloat16_as_ushort(a1) << 16);
        l[i] = (uint32_t)__bfloat16_as_ushort(__float2bfloat16(r0)) |
               ((uint32_t)__bfloat16_as_ushort(__float2bfloat16(r1)) << 16);
    }
    h4 = make_uint4(h[0], h[1], h[2], h[3]);
    l4 = make_uint4(l[0], l[1], l[2], l[3]);
}
__device__ __forceinline__ void split2(float x, float y, uint32_t& h, uint32_t& l) {
    __nv_bfloat16 hx = __float2bfloat16(x), hy = __float2bfloat16(y);
    float rx = x - __bfloat162float(hx), ry = y - __bfloat162float(hy);
    h = (uint32_t)__bfloat16_as_ushort(hx) | ((uint32_t)__bfloat16_as_ushort(hy) << 16);
    l = (uint32_t)__bfloat16_as_ushort(__float2bfloat16(rx)) |
        ((uint32_t)__bfloat16_as_ushort(__float2bfloat16(ry)) << 16);
}

// write 32 fp32 values into the A hi/lo planes at (row, cb)
__device__ __forceinline__ void store_seg(const float* v, char* Ahi, int row, int cb) {
    char* Alo = Ahi + PLANE_A;
#pragma unroll
    for (int g = 0; g < 4; ++g) {
        uint4 h4, l4; cvt8(v + g * 8, h4, l4);
        uint32_t o = (uint32_t)row * PB + (uint32_t)(cb + g * 8) * 2;
        *(uint4*)(Ahi + o) = h4; *(uint4*)(Alo + o) = l4;
    }
}
__device__ __forceinline__ void fill_seg(const float* srcrow, char* Ahi, int row, int cb) {
    if (srcrow) {
        float v[32];
#pragma unroll
        for (int g = 0; g < 8; ++g) *(float4*)(v + g * 4) = *(const float4*)(srcrow + cb + g * 4);
        store_seg(v, Ahi, row, cb);
    } else {
        char* Alo = Ahi + PLANE_A;
        uint4 z = make_uint4(0, 0, 0, 0);
#pragma unroll
        for (int g = 0; g < 4; ++g) {
            uint32_t o = (uint32_t)row * PB + (uint32_t)(cb + g * 8) * 2;
            *(uint4*)(Ahi + o) = z; *(uint4*)(Alo + o) = z;
        }
    }
}

// copy one hi plane (34816B) into smem
__device__ __forceinline__ void cpw(const char* src, char* dst, int tid) {
    const float4* s = (const float4*)src;
    float4* d = (float4*)dst;
#pragma unroll
    for (int i = 0; i < 9; ++i) {
        int idx = tid + i * 256;
        if (idx < HI_B / 16) d[idx] = s[idx];
    }
}

#define ZERO_ACC(acc) do {                       \
    _Pragma("unroll")                            \
    for (int _i = 0; _i < 2; ++_i)               \
        _Pragma("unroll")                        \
        for (int _j = 0; _j < 4; ++_j)           \
            _Pragma("unroll")                    \
            for (int _q = 0; _q < 4; ++_q) (acc)[_i][_j][_q] = 0.f; \
} while (0)

// merged 3-term bf16-split GEMM: acc += Ahi*Whi + Alo*Whi + Ahi*Wlo
// Whi via smem LDSM; Wlo via coalesced gmem LDG.64 from fragment-order blocks.
__device__ __forceinline__ void gemm3(uint32_t Au, uint32_t Wu, const char* __restrict__ wlo,
                                      float (&acc)[2][4][4], int mb, int nb, int lane) {
    uint32_t arow = (uint32_t)(mb + (lane & 15));
    uint32_t aoff = (lane & 16) ? 16u : 0u;
    uint32_t ah = Au + arow * PB + aoff;
    uint32_t al = ah + PLANE_A;
    uint32_t brow = (uint32_t)(nb + (lane & 7) + ((lane & 16) ? 8 : 0));
    uint32_t boff = (lane & 8) ? 16u : 0u;
    uint32_t bh = Wu + brow * PB + boff;
    const char* lp = wlo + (size_t)((nb >> 3) * 8) * 256 + (uint32_t)lane * 8;
#pragma unroll
    for (int ks = 0; ks < 8; ++ks) {
        uint32_t kadd = 32u * ks;
        uint32_t a0h[4], a1h[4], a0l[4], a1l[4];
        ldsm4(a0h, ah + kadd);
        ldsm4(a1h, ah + 16 * PB + kadd);
        ldsm4(a0l, al + kadd);
        ldsm4(a1l, al + 16 * PB + kadd);
        uint32_t b0h[4], b1h[4];
        ldsm4(b0h, bh + kadd);
        ldsm4(b1h, bh + 16 * PB + kadd);
        // hi * hi
        mma16816(acc[0][0], a0h, b0h[0], b0h[1]);
        mma16816(acc[0][1], a0h, b0h[2], b0h[3]);
        mma16816(acc[0][2], a0h, b1h[0], b1h[1]);
        mma16816(acc[0][3], a0h, b1h[2], b1h[3]);
        mma16816(acc[1][0], a1h, b0h[0], b0h[1]);
        mma16816(acc[1][1], a1h, b0h[2], b0h[3]);
        mma16816(acc[1][2], a1h, b1h[0], b1h[1]);
        mma16816(acc[1][3], a1h, b1h[2], b1h[3]);
        // lo * hi
        mma16816(acc[0][0], a0l, b0h[0], b0h[1]);
        mma16816(acc[0][1], a0l, b0h[2], b0h[3]);
        mma16816(acc[0][2], a0l, b1h[0], b1h[1]);
        mma16816(acc[0][3], a0l, b1h[2], b1h[3]);
        mma16816(acc[1][0], a1l, b0h[0], b0h[1]);
        mma16816(acc[1][1], a1l, b0h[2], b0h[3]);
        mma16816(acc[1][2], a1l, b1h[0], b1h[1]);
        mma16816(acc[1][3], a1l, b1h[2], b1h[3]);
        // hi * lo (Wlo fragments from gmem, one 256B-coalesced LDG.64 per n8-tile)
#pragma unroll
        for (int t = 0; t < 4; ++t) {
            uint2 bl = *(const uint2*)(lp + (uint32_t)(t * 8 + ks) * 256);
            mma16816(acc[0][t], a0h, bl.x, bl.y);
            mma16816(acc[1][t], a1h, bl.x, bl.y);
        }
    }
}

// mid-layer: acc -> bias+relu -> bf16 split -> A planes; reset acc
__device__ __forceinline__ void epi_mid(float (&acc)[2][4][4], const float* bias,
                                        char* Ahi, int mb, int nb, int lane) {
    char* Alo = Ahi + PLANE_A;
    int qr = lane >> 2, qc = 2 * (lane & 3);
#pragma unroll
    for (int mt = 0; mt < 2; ++mt) {
#pragma unroll
        for (int nt = 0; nt < 4; ++nt) {
            int c = nb + 8 * nt + qc;
            float b0 = bias[c], b1 = bias[c + 1];
            int r0 = mb + 16 * mt + qr;
            float v00 = fmaxf(acc[mt][nt][0] + b0, 0.f);
            float v01 = fmaxf(acc[mt][nt][1] + b1, 0.f);
            float v10 = fmaxf(acc[mt][nt][2] + b0, 0.f);
            float v11 = fmaxf(acc[mt][nt][3] + b1, 0.f);
            uint32_t h, l;
            uint32_t o0 = (uint32_t)r0 * PB + (uint32_t)c * 2;
            split2(v00, v01, h, l);
            *(uint32_t*)(Ahi + o0) = h; *(uint32_t*)(Alo + o0) = l;
            uint32_t o1 = o0 + 8 * PB;
            split2(v10, v11, h, l);
            *(uint32_t*)(Ahi + o1) = h; *(uint32_t*)(Alo + o1) = l;
            acc[mt][nt][0] = acc[mt][nt][1] = acc[mt][nt][2] = acc[mt][nt][3] = 0.f;
        }
    }
}

// final: acc -> +bias -> fp32 staging (pitch KP floats, overlaid on A planes)
__device__ __forceinline__ void epi_stage(float (&acc)[2][4][4], const float* bias,
                                          float* stage, int mb, int nb, int lane) {
    int qr = lane >> 2, qc = 2 * (lane & 3);
#pragma unroll
    for (int mt = 0; mt < 2; ++mt) {
#pragma unroll
        for (int nt = 0; nt < 4; ++nt) {
            int c = nb + 8 * nt + qc;
            float b0 = bias[c], b1 = bias[c + 1];
            int r0 = mb + 16 * mt + qr;
            *(float2*)(stage + r0 * KP + c)       = make_float2(acc[mt][nt][0] + b0, acc[mt][nt][1] + b1);
            *(float2*)(stage + (r0 + 8) * KP + c) = make_float2(acc[mt][nt][2] + b0, acc[mt][nt][3] + b1);
        }
    }
}

// write acc fragments directly to a [NN, D] fp32 global (P buffers)
__device__ __forceinline__ void write_P(float (&acc)[2][4][4], float* dst,
                                        int base, int mb, int nb, int lane) {
    int qr = lane >> 2, qc = 2 * (lane & 3);
#pragma unroll
    for (int mt = 0; mt < 2; ++mt) {
#pragma unroll
        for (int nt = 0; nt < 4; ++nt) {
            int c = nb + 8 * nt + qc;
            int m0 = base + mb + 16 * mt + qr;
            if (m0 < NN)
                *(float2*)(dst + (size_t)m0 * D + c) = make_float2(acc[mt][nt][0], acc[mt][nt][1]);
            if (m0 + 8 < NN)
                *(float2*)(dst + (size_t)(m0 + 8) * D + c) = make_float2(acc[mt][nt][2], acc[mt][nt][3]);
        }
    }
}

// ---------------- edge kernel (64-edge tile) ----------------
__global__ void __launch_bounds__(256, 3)
edge_kernel(const char* __restrict__ wa, const char* __restrict__ wb, const char* __restrict__ wc,
            const char* __restrict__ w1t, const char* __restrict__ w2t,
            const float* __restrict__ B0, const float* __restrict__ B1, const float* __restrict__ B2,
            const float* __restrict__ G,  const float* __restrict__ Bt,
            const int* __restrict__ eidx, int use_p) {
    extern __shared__ char smem[];
    float* bs = (float*)(smem + SM_BIAS);
    int* sidx = (int*)(smem + SM_SIDX);
    char* Ahi = smem + SM_A;
    char* Wsm = smem + SM_W;
    uint32_t sb = smem_to_u32(smem);
    uint32_t Au = sb + SM_A, Wu = sb + SM_W;
    float* stage = (float*)Ahi;

    const int tid = threadIdx.x, wid = tid >> 5, lane = tid & 31;
    const int base = blockIdx.x * 64;
    const int mb = (wid >> 2) * 32, nb = (wid & 3) * 32;
    const int row = tid >> 2, cb = (tid & 3) * 32;

    if (tid < 64) {
        sidx[tid]      = eidx[base + tid];
        sidx[64 + tid] = eidx[NE + base + tid];
    }
    if (tid < 128) {
        bs[tid]       = B0[tid];
        bs[128 + tid] = B1[tid];
        bs[256 + tid] = B2[tid];
        bs[384 + tid] = G[tid];
        bs[512 + tid] = Bt[tid];
    }
    __syncthreads();

    float acc[2][4][4];

    if (use_p) {
        // stage <- Pa[src] + Pb[dst]
        {
            const float* pa = g_Pa + (size_t)sidx[row] * D + cb;
            const float* pb = g_Pb + (size_t)sidx[64 + row] * D + cb;
            float* st = stage + row * KP + cb;
#pragma unroll
            for (int g = 0; g < 8; ++g) {
                float4 ta = *(const float4*)(pa + g * 4);
                float4 tb = *(const float4*)(pb + g * 4);
                *(float4*)(st + g * 4) = make_float4(ta.x + tb.x, ta.y + tb.y, ta.z + tb.z, ta.w + tb.w);
            }
        }
        __syncthreads();
        {
            int qr = lane >> 2, qc = 2 * (lane & 3);
#pragma unroll
            for (int mt = 0; mt < 2; ++mt) {
#pragma unroll
                for (int nt = 0; nt < 4; ++nt) {
                    int c = nb + 8 * nt + qc;
                    int r0 = mb + 16 * mt + qr;
                    acc[mt][nt][0] = stage[r0 * KP + c];
                    acc[mt][nt][1] = stage[r0 * KP + c + 1];
                    acc[mt][nt][2] = stage[(r0 + 8) * KP + c];
                    acc[mt][nt][3] = stage[(r0 + 8) * KP + c + 1];
                }
            }
        }
        __syncthreads();
        fill_seg(g_e + (size_t)(base + row) * D, Ahi, row, cb);
        cpw(wc, Wsm, tid);
        __syncthreads();
        gemm3(Au, Wu, wc + LO_OFF, acc, mb, nb, lane);
        __syncthreads();
    } else {
        ZERO_ACC(acc);
#pragma unroll 1
        for (int s = 0; s < 3; ++s) {
            const char* wt = (s == 0) ? wa : (s == 1) ? wb : wc;
            const float* src;
            if (s == 0)      src = g_x + (size_t)sidx[row] * D;
            else if (s == 1) src = g_x + (size_t)sidx[64 + row] * D;
            else             src = g_e + (size_t)(base + row) * D;
            fill_seg(src, Ahi, row, cb);
            cpw(wt, Wsm, tid);
            __syncthreads();
            gemm3(Au, Wu, wt + LO_OFF, acc, mb, nb, lane);
            __syncthreads();
        }
    }

    epi_mid(acc, bs, Ahi, mb, nb, lane);
    cpw(w1t, Wsm, tid);
    __syncthreads();
    gemm3(Au, Wu, w1t + LO_OFF, acc, mb, nb, lane);
    __syncthreads();

    epi_mid(acc, bs + 128, Ahi, mb, nb, lane);
    cpw(w2t, Wsm, tid);
    __syncthreads();
    gemm3(Au, Wu, w2t + LO_OFF, acc, mb, nb, lane);
    __syncthreads();

    epi_stage(acc, bs + 256, stage, mb, nb, lane);
    __syncthreads();

    // LN + residual + store (node kernel gathers via CSR)
#pragma unroll 1
    for (int r = wid; r < 64; r += 8) {
        const float* st = stage + r * KP;
        int c = lane * 4;
        float4 v = *(const float4*)(st + c);
        float s1 = v.x + v.y + v.z + v.w;
        float s2 = v.x * v.x + v.y * v.y + v.z * v.z + v.w * v.w;
#pragma unroll
        for (int o = 16; o; o >>= 1) {
            s1 += __shfl_xor_sync(0xffffffffu, s1, o);
            s2 += __shfl_xor_sync(0xffffffffu, s2, o);
        }
        float mean = s1 * (1.f / D);
        float var  = s2 * (1.f / D) - mean * mean;
        float rstd = rsqrtf(var + EPSLN);
        float4 gm = *(const float4*)(bs + 384 + c);
        float4 bt = *(const float4*)(bs + 512 + c);
        float* erow = g_e + (size_t)(base + r) * D;
        float4 res = *(const float4*)(erow + c);
        float4 y;
        y.x = gm.x * (v.x - mean) * rstd + bt.x + res.x;
        y.y = gm.y * (v.y - mean) * rstd + bt.y + res.y;
        y.z = gm.z * (v.z - mean) * rstd + bt.z + res.z;
        y.w = gm.w * (v.w - mean) * rstd + bt.w + res.w;
        *(float4*)(erow + c) = y;
    }
}

// ---------------- node kernel (64-node tile, CSR gather; fused next-iter P) ----------------
__global__ void __launch_bounds__(256, 3)
node_kernel(const char* __restrict__ w0t, const char* __restrict__ w1t, const char* __restrict__ w2t,
            const float* __restrict__ B0, const float* __restrict__ B1, const float* __restrict__ B2,
            const float* __restrict__ G,  const float* __restrict__ Bt,
            const char* __restrict__ wea, const char* __restrict__ web, int has_next) {
    extern __shared__ char smem[];
    float* bs = (float*)(smem + SM_BIAS);
    char* Ahi = smem + SM_A;
    char* Wsm = smem + SM_W;
    uint32_t sb = smem_to_u32(smem);
    uint32_t Au = sb + SM_A, Wu = sb + SM_W;
    float* stage = (float*)Ahi;

    const int tid = threadIdx.x, wid = tid >> 5, lane = tid & 31;
    const int base = blockIdx.x * 64;
    const int mb = (wid >> 2) * 32, nb = (wid & 3) * 32;
    const int row = tid >> 2, cb = (tid & 3) * 32;
    const int m = base + row;

    if (tid < 128) {
        bs[tid]       = B0[tid];
        bs[128 + tid] = B1[tid];
        bs[256 + tid] = B2[tid];
        bs[384 + tid] = G[tid];
        bs[512 + tid] = Bt[tid];
    }
    __syncthreads();

    float acc[2][4][4];
    ZERO_ACC(acc);

    // layer 0 segment 0: x
    fill_seg((m < NN) ? (g_x + (size_t)m * D) : (const float*)0, Ahi, row, cb);
    cpw(w0t, Wsm, tid);
    __syncthreads();
    gemm3(Au, Wu, w0t + LO_OFF, acc, mb, nb, lane);
    __syncthreads();

    // layer 0 segment 1: agg = CSR gather-sum of this iteration's edge features
    {
        float v[32];
#pragma unroll
        for (int j = 0; j < 32; ++j) v[j] = 0.f;
        if (m < NN) {
            int p0 = g_off[m], p1 = g_off[m + 1];
#pragma unroll 1
            for (int p = p0; p < p1; ++p) {
                const float* er = g_e + (size_t)g_csr[p] * D + cb;
#pragma unroll
                for (int g = 0; g < 8; ++g) {
                    float4 t = *(const float4*)(er + g * 4);
                    v[g * 4 + 0] += t.x; v[g * 4 + 1] += t.y;
                    v[g * 4 + 2] += t.z; v[g * 4 + 3] += t.w;
                }
            }
        }
        store_seg(v, Ahi, row, cb);
        cpw(w0t + TILE_B, Wsm, tid);
        __syncthreads();
        gemm3(Au, Wu, w0t + TILE_B + LO_OFF, acc, mb, nb, lane);
        __syncthreads();
    }

    epi_mid(acc, bs, Ahi, mb, nb, lane);
    cpw(w1t, Wsm, tid);
    __syncthreads();
    gemm3(Au, Wu, w1t + LO_OFF, acc, mb, nb, lane);
    __syncthreads();

    epi_mid(acc, bs + 128, Ahi, mb, nb, lane);
    cpw(w2t, Wsm, tid);
    __syncthreads();
    gemm3(Au, Wu, w2t + LO_OFF, acc, mb, nb, lane);
    __syncthreads();

    epi_stage(acc, bs + 256, stage, mb, nb, lane);
    __syncthreads();

    // LN + residual -> new x; keep new x in stage for the fused P GEMMs
#pragma unroll 1
    for (int r = wid; r < 64; r += 8) {
        int mm = base + r;
        float* st = stage + r * KP;
        int c = lane * 4;
        float4 v = *(const float4*)(st + c);
        float s1 = v.x + v.y + v.z + v.w;
        float s2 = v.x * v.x + v.y * v.y + v.z * v.z + v.w * v.w;
#pragma unroll
        for (int o = 16; o; o >>= 1) {
            s1 += __shfl_xor_sync(0xffffffffu, s1, o);
            s2 += __shfl_xor_sync(0xffffffffu, s2, o);
        }
        float mean = s1 * (1.f / D);
        float var  = s2 * (1.f / D) - mean * mean;
        float rstd = rsqrtf(var + EPSLN);
        float4 gm = *(const float4*)(bs + 384 + c);
        float4 bt = *(const float4*)(bs + 512 + c);
        if (mm < NN) {
            float* xrow = g_x + (size_t)mm * D;
            float4 res = *(const float4*)(xrow + c);
            float4 y;
            y.x = gm.x * (v.x - mean) * rstd + bt.x + res.x;
            y.y = gm.y * (v.y - mean) * rstd + bt.y + res.y;
            y.z = gm.z * (v.z - mean) * rstd + bt.z + res.z;
            y.w = gm.w * (v.w - mean) * rstd + bt.w + res.w;
            *(float4*)(xrow + c) = y;
            *(float4*)(st + c) = y;
        }
    }

    if (!has_next) return;

    // ---- fused: P = new_x @ eW0{a,b} for the NEXT iteration ----
    __syncthreads();
    float v[32];
#pragma unroll
    for (int g = 0; g < 8; ++g) *(float4*)(v + g * 4) = *(const float4*)(stage + row * KP + cb + g * 4);
    __syncthreads();
    store_seg(v, Ahi, row, cb);
    cpw(wea, Wsm, tid);
    __syncthreads();
    ZERO_ACC(acc);
    gemm3(Au, Wu, wea + LO_OFF, acc, mb, nb, lane);
    __syncthreads();
    write_P(acc, g_Pa, base, mb, nb, lane);
    cpw(web, Wsm, tid);
    __syncthreads();
    ZERO_ACC(acc);
    gemm3(Au, Wu, web + LO_OFF, acc, mb, nb, lane);
    write_P(acc, g_Pb, base, mb, nb, lane);
}

// ---------------- CSR build (once per launch) ----------------
__global__ void zero_k() {
    int i = blockIdx.x * blockDim.x + threadIdx.x;
    if (i < NN) g_cur[i] = 0;
}
__global__ void hist_k(const int* __restrict__ eidx) {
    int i = blockIdx.x * blockDim.x + threadIdx.x;
    if (i < NE) atomicAdd(&g_cur[eidx[NE + i]], 1);
}
__global__ void __launch_bounds__(1024, 1) scan_k() {
    __shared__ int part[1024];
    const int t = threadIdx.x;
    const int per = (NN + 1023) / 1024;
    int s = 0;
#pragma unroll 1
    for (int j = 0; j < per; ++j) {
        int idx = t * per + j;
        if (idx < NN) s += g_cur[idx];
    }
    part[t] = s;
    __syncthreads();
#pragma unroll 1
    for (int o = 1; o < 1024; o <<= 1) {
        int add = (t >= o) ? part[t - o] : 0;
        __syncthreads();
        part[t] += add;
        __syncthreads();
    }
    int base = (t == 0) ? 0 : part[t - 1];
#pragma unroll 1
    for (int j = 0; j < per; ++j) {
        int idx = t * per + j;
        if (idx < NN) {
            g_off[idx] = base;
            base += g_cur[idx];
            g_cur[idx] = 0;
        }
    }
    if (t == 1023) g_off[NN] = part[1023];
}
__global__ void fillcsr_k(const int* __restrict__ eidx) {
    int i = blockIdx.x * blockDim.x + threadIdx.x;
    if (i < NE) {
        int d = eidx[NE + i];
        int p = atomicAdd(&g_cur[d], 1);
        g_csr[g_off[d] + p] = i;
    }
}

// ---------------- weight prep (single launch, 135 tiles) ----------------
// hi plane: [n][k] bf16 pitch 272B. lo plane: fragment blocks — block (n8,ks) is 256B;
// lane l holds uint2 { pair(k=2(l&3)+{0,1}, n=n8*8+l/4), pair(k+8) }.
__global__ void __launch_bounds__(256, 1)
prep_all(const float* __restrict__ eW0, const float* __restrict__ eW1, const float* __restrict__ eW2,
         const float* __restrict__ nW0, const float* __restrict__ nW1, const float* __restrict__ nW2,
         char* __restrict__ dst) {
    const int t = blockIdx.x, tid = threadIdx.x;
    const float* s;
    if (t < 45)       s = eW0 + (size_t)t * 16384;
    else if (t < 60)  s = eW1 + (size_t)(t - 45) * 16384;
    else if (t < 75)  s = eW2 + (size_t)(t - 60) * 16384;
    else if (t < 105) s = nW0 + (size_t)(t - 75) * 16384;
    else if (t < 120) s = nW1 + (size_t)(t - 105) * 16384;
    else              s = nW2 + (size_t)(t - 120) * 16384;
    char* hi = dst + (size_t)t * TILE_B;
    char* lo = hi + LO_OFF;
    const int n = tid >> 1, kb = (tid & 1) * 64;
    const int n8 = n >> 3, nr = n & 7;
#pragma unroll 1
    for (int g = 0; g < 8; ++g) {
        int k0 = kb + g * 8;
        float v[8];
#pragma unroll
        for (int j = 0; j < 8; ++j) v[j] = s[(size_t)(k0 + j) * 128 + n];
        uint4 h4, l4; cvt8(v, h4, l4);
        *(uint4*)(hi + (uint32_t)n * PB + (uint32_t)k0 * 2) = h4;
        int ks = k0 >> 4, half = (k0 >> 3) & 1;
        char* bp = lo + (uint32_t)(n8 * 8 + ks) * 256 + (uint32_t)half * 4;
        *(uint32_t*)(bp + (nr * 4 + 0) * 8) = l4.x;
        *(uint32_t*)(bp + (nr * 4 + 1) * 8) = l4.y;
        *(uint32_t*)(bp + (nr * 4 + 2) * 8) = l4.z;
        *(uint32_t*)(bp + (nr * 4 + 3) * 8) = l4.w;
    }
}

// ---------------- host launch (graph-capturable) ----------------
extern "C" void kernel_launch(void* const* d_in, const int* in_sizes, int n_in,
                              void* d_out, int out_size) {
    const float* x    = (const float*)d_in[0];
    const float* ea   = (const float*)d_in[1];
    const float* eW0  = (const float*)d_in[2];
    const float* eB0  = (const float*)d_in[3];
    const float* eW1  = (const float*)d_in[4];
    const float* eB1  = (const float*)d_in[5];
    const float* eW2  = (const float*)d_in[6];
    const float* eB2  = (const float*)d_in[7];
    const float* eG   = (const float*)d_in[8];
    const float* eBt  = (const float*)d_in[9];
    const float* nW0  = (const float*)d_in[10];
    const float* nB0  = (const float*)d_in[11];
    const float* nW1  = (const float*)d_in[12];
    const float* nB1  = (const float*)d_in[13];
    const float* nW2  = (const float*)d_in[14];
    const float* nB2  = (const float*)d_in[15];
    const float* nG   = (const float*)d_in[16];
    const float* nBt  = (const float*)d_in[17];
    const int*   eidx = (const int*)d_in[18];

    float *px, *pe;
    char* pwb;
    cudaGetSymbolAddress((void**)&px,  g_x);
    cudaGetSymbolAddress((void**)&pe,  g_e);
    cudaGetSymbolAddress((void**)&pwb, g_wb);

    cudaFuncSetAttribute(edge_kernel, cudaFuncAttributeMaxDynamicSharedMemorySize, SMEM_TOTAL);
    cudaFuncSetAttribute(node_kernel, cudaFuncAttributeMaxDynamicSharedMemorySize, SMEM_TOTAL);

    cudaMemcpyAsync(px, x,  (size_t)NN * D * sizeof(float), cudaMemcpyDeviceToDevice);
    cudaMemcpyAsync(pe, ea, (size_t)NE * D * sizeof(float), cudaMemcpyDeviceToDevice);

    // 5 prep kernels, then edge_kernel is the 6th launch (ncu -s 5 -c 1 captures it)
    zero_k<<<(NN + 255) / 256, 256>>>();
    hist_k<<<(NE + 255) / 256, 256>>>(eidx);
    scan_k<<<1, 1024>>>();
    fillcsr_k<<<(NE + 255) / 256, 256>>>(eidx);
    prep_all<<<NTILES, 256>>>(eW0, eW1, eW2, nW0, nW1, nW2, pwb);

    const int NB = (NN + 63) / 64;   // 313
    for (int it = 0; it < ITERS; ++it) {
        edge_kernel<<<NE / 64, 256, SMEM_TOTAL>>>(
            pwb + (size_t)(it * 3)      * TILE_B,
            pwb + (size_t)(it * 3 + 1)  * TILE_B,
            pwb + (size_t)(it * 3 + 2)  * TILE_B,
            pwb + (size_t)(45 + it)     * TILE_B,
            pwb + (size_t)(60 + it)     * TILE_B,
            eB0 + it * D, eB1 + it * D, eB2 + it * D,
            eG + it * D, eBt + it * D, eidx, (it > 0) ? 1 : 0);
        node_kernel<<<NB, 256, SMEM_TOTAL>>>(
            pwb + (size_t)(75 + it * 2) * TILE_B,
            pwb + (size_t)(105 + it)    * TILE_B,
            pwb + (size_t)(120 + it)    * TILE_B,
            nB0 + it * D, nB1 + it * D, nB2 + it * D,
            nG + it * D, nBt + it * D,
            pwb + (size_t)((it + 1) * 3)     * TILE_B,
            pwb + (size_t)((it + 1) * 3 + 1) * TILE_B,
            (it < ITERS - 1) ? 1 : 0);
    }

    cudaMemcpyAsync(d_out, px, (size_t)NN * D * sizeof(float), cudaMemcpyDeviceToDevice);
    cudaMemcpyAsync((float*)d_out + (size_t)NN * D, pe,
                    (size_t)NE * D * sizeof(float), cudaMemcpyDeviceToDevice);
}